// round 8
// baseline (speedup 1.0000x reference)
#include <cuda_runtime.h>
#include <stdint.h>

// Problem constants
#define B_   256
#define T_   256
#define C_   384
#define NH_  8
#define HD_  48
#define M_   (B_ * T_)        // 65536 rows
#define N1_  (3 * C_)         // 1152 qkv outputs
#define QKV_STRIDE 25165824   // B*T*C elements per q/k/v region

// Scratch (allocation-guard-safe: static __device__ globals)
__device__ float g_qkv[3ull * QKV_STRIDE];   // [3][B][NH][T][HD]
__device__ float g_att[(size_t)QKV_STRIDE];  // [B][T][C]

// ---------------------------------------------------------------------------
// tf32 helpers
// ---------------------------------------------------------------------------
__device__ __forceinline__ uint32_t f2tf(float f) {
    uint32_t u;
    asm("cvt.rna.tf32.f32 %0, %1;" : "=r"(u) : "f"(f));
    return u;
}

__device__ __forceinline__ void mma_tf32(
    float& c0, float& c1, float& c2, float& c3,
    uint32_t a0, uint32_t a1, uint32_t a2, uint32_t a3,
    uint32_t b0, uint32_t b1)
{
    asm volatile(
        "mma.sync.aligned.m16n8k8.row.col.f32.tf32.tf32.f32 "
        "{%0,%1,%2,%3}, {%4,%5,%6,%7}, {%8,%9}, {%0,%1,%2,%3};"
        : "+f"(c0), "+f"(c1), "+f"(c2), "+f"(c3)
        : "r"(a0), "r"(a1), "r"(a2), "r"(a3), "r"(b0), "r"(b1));
}

// ---------------------------------------------------------------------------
// tf32 GEMM core: CTA 128x128, BK=16, 256 thr = 8 warps (2m x 4n),
// warp tile 64x32 = 4x4 m16n8k8 atoms.  DOUBLE-BUFFERED fragment-order smem
// (16 KB A + 16 KB B total), one barrier per k-tile; 2 CTAs/SM.
//
// Fragment-order layout (tf32 converted once at staging, wide-LDS reads):
//  A chunk (kb, am): 128 words; element (m,k): am=m>>4, r8=(m>>3)&1, kb=k>>3,
//    ctg=k&3, khalf=(k>>2)&1 ->
//    word (kb*8+am)*128 + (((m&7)*4+ctg+kb)&31)*4 + r8 + 2*khalf
//    Reader: one LDS.128 per atom (lane slot (lane+kb)&31) -> conflict-free.
//  B chunk (kb, an): 64 words;
//    word (kb*16+an)*64 + (((n&7)*4+ctg+kb)&31)*2 + khalf
//    Reader: one LDS.64 per atom -> conflict-free.
// K sweep 0..383 ascending -> accumulation bit-identical to R4..R7.
// ---------------------------------------------------------------------------
#define ABUF 2048   // words per A buffer (128 x 16)
#define BBUF 2048   // words per B buffer

struct GemmFrag {
    float acc[4][4][4];   // [m-atom][n-atom][reg]
    int gid, ctg, wmB, wnB;
};

__device__ __forceinline__ void gemm_core(
    const float* __restrict__ A, const float* __restrict__ W,
    int mBase, int nBase, uint32_t* As, uint32_t* Bs, GemmFrag& f)
{
    const int tid  = threadIdx.x;
    const int lane = tid & 31;
    const int warp = tid >> 5;
    f.gid = lane >> 2;
    f.ctg = lane & 3;
    f.wmB = (warp >> 2) * 64;   // 0, 64
    f.wnB = (warp & 3) * 32;    // 0,32,64,96

#pragma unroll
    for (int i = 0; i < 4; ++i)
#pragma unroll
        for (int j = 0; j < 4; ++j)
#pragma unroll
            for (int r = 0; r < 4; ++r) f.acc[i][j][r] = 0.f;

    // staging mapping: thread -> row lrow (0..127), k-halfchunk lkc (0 or 8).
    const int lrow = tid >> 1;
    const int lkc  = (tid & 1) * 8;
    const int kb_s = lkc >> 3;           // 0 or 1

    const int aW  = (kb_s * 8  + (lrow >> 4)) * 128 + ((lrow >> 3) & 1);
    const int bW  = (kb_s * 16 + (lrow >> 3)) * 64;
    const int aLS = (lrow & 7) * 4 + kb_s;
    const int bLS = aLS;

    const float* gA = A + (size_t)(mBase + lrow) * 384 + lkc;
    const float* gW = W + (size_t)(nBase + lrow) * 384 + lkc;

    const int amB = f.wmB >> 4;
    const int anB = f.wnB >> 3;

    float4 ra0, ra1, rb0, rb1;

    // prologue: stage tile 0 into buf0, prefetch tile 1 into regs
    ra0 = *(const float4*)(gA);
    ra1 = *(const float4*)(gA + 4);
    rb0 = *(const float4*)(gW);
    rb1 = *(const float4*)(gW + 4);
    {
        const float va0[4] = {ra0.x, ra0.y, ra0.z, ra0.w};
        const float va1[4] = {ra1.x, ra1.y, ra1.z, ra1.w};
        const float vb0[4] = {rb0.x, rb0.y, rb0.z, rb0.w};
        const float vb1[4] = {rb1.x, rb1.y, rb1.z, rb1.w};
#pragma unroll
        for (int c = 0; c < 4; ++c) {
            const int ls = ((aLS + c) & 31);
            As[aW + ls * 4]     = f2tf(va0[c]);
            As[aW + ls * 4 + 2] = f2tf(va1[c]);
            Bs[bW + ls * 2]     = f2tf(vb0[c]);
            Bs[bW + ls * 2 + 1] = f2tf(vb1[c]);
        }
    }
    ra0 = *(const float4*)(gA + 16);
    ra1 = *(const float4*)(gA + 20);
    rb0 = *(const float4*)(gW + 16);
    rb1 = *(const float4*)(gW + 20);
    __syncthreads();

    for (int t = 0; t < 24; ++t) {
        const uint32_t* Ab = As + (t & 1) * ABUF;
        const uint32_t* Bb = Bs + (t & 1) * BBUF;

#pragma unroll
        for (int kb = 0; kb < 2; ++kb) {
            const int lsw = (lane + kb) & 31;
            uint32_t a[4][4], b[4][2];
#pragma unroll
            for (int im = 0; im < 4; ++im) {
                const uint4 t4 = *(const uint4*)&Ab[(kb * 8 + amB + im) * 128 + lsw * 4];
                a[im][0] = t4.x; a[im][1] = t4.y; a[im][2] = t4.z; a[im][3] = t4.w;
            }
#pragma unroll
            for (int jn = 0; jn < 4; ++jn) {
                const uint2 t2 = *(const uint2*)&Bb[(kb * 16 + anB + jn) * 64 + lsw * 2];
                b[jn][0] = t2.x; b[jn][1] = t2.y;
            }
#pragma unroll
            for (int im = 0; im < 4; ++im)
#pragma unroll
                for (int jn = 0; jn < 4; ++jn)
                    mma_tf32(f.acc[im][jn][0], f.acc[im][jn][1],
                             f.acc[im][jn][2], f.acc[im][jn][3],
                             a[im][0], a[im][1], a[im][2], a[im][3],
                             b[jn][0], b[jn][1]);
        }

        if (t < 23) {
            // stage tile t+1 (regs) into the other buffer — overlaps compute
            uint32_t* An = As + ((t + 1) & 1) * ABUF;
            uint32_t* Bn = Bs + ((t + 1) & 1) * BBUF;
            const float va0[4] = {ra0.x, ra0.y, ra0.z, ra0.w};
            const float va1[4] = {ra1.x, ra1.y, ra1.z, ra1.w};
            const float vb0[4] = {rb0.x, rb0.y, rb0.z, rb0.w};
            const float vb1[4] = {rb1.x, rb1.y, rb1.z, rb1.w};
#pragma unroll
            for (int c = 0; c < 4; ++c) {
                const int ls = ((aLS + c) & 31);
                An[aW + ls * 4]     = f2tf(va0[c]);
                An[aW + ls * 4 + 2] = f2tf(va1[c]);
                Bn[bW + ls * 2]     = f2tf(vb0[c]);
                Bn[bW + ls * 2 + 1] = f2tf(vb1[c]);
            }
            if (t < 22) {   // prefetch tile t+2
                const int kt = (t + 2) * 16;
                ra0 = *(const float4*)(gA + kt);
                ra1 = *(const float4*)(gA + kt + 4);
                rb0 = *(const float4*)(gW + kt);
                rb1 = *(const float4*)(gW + kt + 4);
            }
        }
        __syncthreads();
    }
}

// ---------------------------------------------------------------------------
// GEMM 1: qkv = x @ attn_w^T + attn_b, scattered head-major into g_qkv.
// ---------------------------------------------------------------------------
__global__ __launch_bounds__(256, 2) void gemm_qkv_kernel(
    const float* __restrict__ A,
    const float* __restrict__ W,
    const float* __restrict__ bias)
{
    __shared__ uint32_t As[2 * ABUF];   // 16 KB
    __shared__ uint32_t Bs[2 * BBUF];   // 16 KB
    const int mBase = blockIdx.y * 128;
    const int nBase = blockIdx.x * 128;

    GemmFrag f;
    gemm_core(A, W, mBase, nBase, As, Bs, f);

#pragma unroll
    for (int im = 0; im < 4; ++im) {
#pragma unroll
        for (int jn = 0; jn < 4; ++jn) {
            const int col = nBase + f.wnB + jn * 8 + 2 * f.ctg;
            const float2 bi = *(const float2*)(bias + col);
            const int which = col / C_;
            const int c = col - which * C_;
            const int h = c / HD_;
            const int d = c - h * HD_;   // even; pair never straddles a head
#pragma unroll
            for (int half = 0; half < 2; ++half) {
                const int row = mBase + f.wmB + im * 16 + f.gid + half * 8;
                const int b = row >> 8;
                const int t = row & 255;
                float2 v;
                v.x = f.acc[im][jn][half * 2 + 0] + bi.x;
                v.y = f.acc[im][jn][half * 2 + 1] + bi.y;
                const size_t dst = (size_t)which * QKV_STRIDE
                                 + ((size_t)((b * NH_ + h) * T_ + t)) * HD_ + d;
                *(float2*)(g_qkv + dst) = v;
            }
        }
    }
}

// ---------------------------------------------------------------------------
// GEMM 2: out = g_att @ proj_w^T + proj_b.
// ---------------------------------------------------------------------------
__global__ __launch_bounds__(256, 2) void gemm_proj_kernel(
    const float* __restrict__ W,
    const float* __restrict__ bias,
    float* __restrict__ out)
{
    __shared__ uint32_t As[2 * ABUF];
    __shared__ uint32_t Bs[2 * BBUF];
    const int mBase = blockIdx.y * 128;
    const int nBase = blockIdx.x * 128;

    GemmFrag f;
    gemm_core(g_att, W, mBase, nBase, As, Bs, f);

#pragma unroll
    for (int im = 0; im < 4; ++im) {
#pragma unroll
        for (int jn = 0; jn < 4; ++jn) {
            const int col = nBase + f.wnB + jn * 8 + 2 * f.ctg;
            const float2 bi = *(const float2*)(bias + col);
#pragma unroll
            for (int half = 0; half < 2; ++half) {
                const int row = mBase + f.wmB + im * 16 + f.gid + half * 8;
                float2 v;
                v.x = f.acc[im][jn][half * 2 + 0] + bi.x;
                v.y = f.acc[im][jn][half * 2 + 1] + bi.y;
                *(float2*)(out + (size_t)row * C_ + col) = v;
            }
        }
    }
}

// ---------------------------------------------------------------------------
// Flash attention, tf32 tensor cores (unchanged from R6).
// ---------------------------------------------------------------------------
#define KSTR 52
#define VSTR 68

__global__ __launch_bounds__(256) void attn_kernel()
{
    __shared__ uint32_t sK[64 * KSTR];
    __shared__ uint32_t sVT[48 * VSTR];

    const int bh = blockIdx.x;
    const int qt = blockIdx.y;
    const int qb = qt * 128;
    const size_t base = (size_t)bh * (T_ * HD_);
    const float* Qg = g_qkv + base;
    const float* Kg = g_qkv + (size_t)QKV_STRIDE + base;
    const float* Vg = g_qkv + 2ull * QKV_STRIDE + base;

    const int tid  = threadIdx.x;
    const int lane = tid & 31;
    const int wid  = tid >> 5;
    const int gid  = lane >> 2;
    const int ctg  = lane & 3;

    const int r0  = wid * 16 + gid;
    const int r1  = r0 + 8;
    const int gr0 = qb + r0;
    const int gr1 = qb + r1;

    const float scale   = 0.14433756729740645f;   // 1/sqrt(48)
    const float NEG_INF = __int_as_float(0xff800000);

    uint32_t aq[6][4];
#pragma unroll
    for (int kb = 0; kb < 6; ++kb) {
        aq[kb][0] = f2tf(Qg[(size_t)gr0 * HD_ + kb * 8 + ctg]     * scale);
        aq[kb][1] = f2tf(Qg[(size_t)gr1 * HD_ + kb * 8 + ctg]     * scale);
        aq[kb][2] = f2tf(Qg[(size_t)gr0 * HD_ + kb * 8 + ctg + 4] * scale);
        aq[kb][3] = f2tf(Qg[(size_t)gr1 * HD_ + kb * 8 + ctg + 4] * scale);
    }

    float m0 = NEG_INF, m1 = NEG_INF, l0 = 0.f, l1 = 0.f;
    float o[6][4];
#pragma unroll
    for (int n = 0; n < 6; ++n)
#pragma unroll
        for (int r = 0; r < 4; ++r) o[n][r] = 0.f;

    const int npass = 2 * (qt + 1);
    for (int j = 0; j < npass; ++j) {
        const int jb = j * 64;
        __syncthreads();

#pragma unroll
        for (int i = 0; i < 3; ++i) {
            const int idx = tid + i * 256;
            const int r   = idx / 12;
            const int c4  = (idx % 12) * 4;
            const float4 kv = *(const float4*)(Kg + (size_t)(jb + r) * HD_ + c4);
            uint4 kt;
            kt.x = f2tf(kv.x); kt.y = f2tf(kv.y);
            kt.z = f2tf(kv.z); kt.w = f2tf(kv.w);
            *(uint4*)(sK + r * KSTR + c4) = kt;
            const float4 vv = *(const float4*)(Vg + (size_t)(jb + r) * HD_ + c4);
            sVT[(c4 + 0) * VSTR + r] = f2tf(vv.x);
            sVT[(c4 + 1) * VSTR + r] = f2tf(vv.y);
            sVT[(c4 + 2) * VSTR + r] = f2tf(vv.z);
            sVT[(c4 + 3) * VSTR + r] = f2tf(vv.w);
        }
        __syncthreads();

        if (jb > qb + wid * 16 + 15) continue;

        float s[8][4];
#pragma unroll
        for (int nb = 0; nb < 8; ++nb) {
            s[nb][0] = 0.f; s[nb][1] = 0.f; s[nb][2] = 0.f; s[nb][3] = 0.f;
#pragma unroll
            for (int kb = 0; kb < 6; ++kb) {
                const uint32_t b0 = sK[(nb * 8 + gid) * KSTR + kb * 8 + ctg];
                const uint32_t b1 = sK[(nb * 8 + gid) * KSTR + kb * 8 + ctg + 4];
                mma_tf32(s[nb][0], s[nb][1], s[nb][2], s[nb][3],
                         aq[kb][0], aq[kb][1], aq[kb][2], aq[kb][3], b0, b1);
            }
        }

        float tmax0 = NEG_INF, tmax1 = NEG_INF;
#pragma unroll
        for (int nb = 0; nb < 8; ++nb) {
            const int k0 = jb + nb * 8 + 2 * ctg;
            const int k1 = k0 + 1;
            if (k0 > gr0) s[nb][0] = NEG_INF;
            if (k1 > gr0) s[nb][1] = NEG_INF;
            if (k0 > gr1) s[nb][2] = NEG_INF;
            if (k1 > gr1) s[nb][3] = NEG_INF;
            tmax0 = fmaxf(tmax0, fmaxf(s[nb][0], s[nb][1]));
            tmax1 = fmaxf(tmax1, fmaxf(s[nb][2], s[nb][3]));
        }
        tmax0 = fmaxf(tmax0, __shfl_xor_sync(0xffffffffu, tmax0, 1));
        tmax0 = fmaxf(tmax0, __shfl_xor_sync(0xffffffffu, tmax0, 2));
        tmax1 = fmaxf(tmax1, __shfl_xor_sync(0xffffffffu, tmax1, 1));
        tmax1 = fmaxf(tmax1, __shfl_xor_sync(0xffffffffu, tmax1, 2));

        const float mn0 = fmaxf(m0, tmax0);
        const float mn1 = fmaxf(m1, tmax1);
        const float corr0 = __expf(m0 - mn0);
        const float corr1 = __expf(m1 - mn1);
        m0 = mn0; m1 = mn1;

        float ps0 = 0.f, ps1 = 0.f;
#pragma unroll
        for (int nb = 0; nb < 8; ++nb) {
            s[nb][0] = __expf(s[nb][0] - mn0);
            s[nb][1] = __expf(s[nb][1] - mn0);
            s[nb][2] = __expf(s[nb][2] - mn1);
            s[nb][3] = __expf(s[nb][3] - mn1);
            ps0 += s[nb][0] + s[nb][1];
            ps1 += s[nb][2] + s[nb][3];
        }
        ps0 += __shfl_xor_sync(0xffffffffu, ps0, 1);
        ps0 += __shfl_xor_sync(0xffffffffu, ps0, 2);
        ps1 += __shfl_xor_sync(0xffffffffu, ps1, 1);
        ps1 += __shfl_xor_sync(0xffffffffu, ps1, 2);
        l0 = l0 * corr0 + ps0;
        l1 = l1 * corr1 + ps1;

#pragma unroll
        for (int n = 0; n < 6; ++n) {
            o[n][0] *= corr0; o[n][1] *= corr0;
            o[n][2] *= corr1; o[n][3] *= corr1;
        }

        const int src0 = (lane & ~3) | (ctg >> 1);
        const int src1 = src0 + 2;
        const bool odd = ctg & 1;
#pragma unroll
        for (int kb = 0; kb < 8; ++kb) {
            const float v00 = __shfl_sync(0xffffffffu, s[kb][0], src0);
            const float v01 = __shfl_sync(0xffffffffu, s[kb][1], src0);
            const float v02 = __shfl_sync(0xffffffffu, s[kb][2], src0);
            const float v03 = __shfl_sync(0xffffffffu, s[kb][3], src0);
            const float v10 = __shfl_sync(0xffffffffu, s[kb][0], src1);
            const float v11 = __shfl_sync(0xffffffffu, s[kb][1], src1);
            const float v12 = __shfl_sync(0xffffffffu, s[kb][2], src1);
            const float v13 = __shfl_sync(0xffffffffu, s[kb][3], src1);
            uint32_t a0 = f2tf(odd ? v01 : v00);
            uint32_t a1 = f2tf(odd ? v03 : v02);
            uint32_t a2 = f2tf(odd ? v11 : v10);
            uint32_t a3 = f2tf(odd ? v13 : v12);
#pragma unroll
            for (int nb = 0; nb < 6; ++nb) {
                const uint32_t b0 = sVT[(nb * 8 + gid) * VSTR + kb * 8 + ctg];
                const uint32_t b1 = sVT[(nb * 8 + gid) * VSTR + kb * 8 + ctg + 4];
                mma_tf32(o[nb][0], o[nb][1], o[nb][2], o[nb][3],
                         a0, a1, a2, a3, b0, b1);
            }
        }
    }

    const float inv0 = 1.f / l0;
    const float inv1 = 1.f / l1;
    const int b = bh >> 3, h = bh & 7;
    float* dst0 = g_att + (size_t)(b * T_ + gr0) * C_ + h * HD_;
    float* dst1 = g_att + (size_t)(b * T_ + gr1) * C_ + h * HD_;
#pragma unroll
    for (int nb = 0; nb < 6; ++nb) {
        const int col = nb * 8 + 2 * ctg;
        float2 v0, v1;
        v0.x = o[nb][0] * inv0; v0.y = o[nb][1] * inv0;
        v1.x = o[nb][2] * inv1; v1.y = o[nb][3] * inv1;
        *(float2*)(dst0 + col) = v0;
        *(float2*)(dst1 + col) = v1;
    }
}

// ---------------------------------------------------------------------------
extern "C" void kernel_launch(void* const* d_in, const int* in_sizes, int n_in,
                              void* d_out, int out_size)
{
    const float* x      = (const float*)d_in[0];
    const float* attn_w = (const float*)d_in[1];
    const float* attn_b = (const float*)d_in[2];
    const float* proj_w = (const float*)d_in[3];
    const float* proj_b = (const float*)d_in[4];
    float* out = (float*)d_out;

    gemm_qkv_kernel<<<dim3(N1_ / 128, M_ / 128), 256>>>(x, attn_w, attn_b);
    attn_kernel<<<dim3(B_ * NH_, 2), 256>>>();
    gemm_proj_kernel<<<dim3(C_ / 128, M_ / 128), 256>>>(proj_w, proj_b, out);
}

// round 10
// speedup vs baseline: 1.1091x; 1.1091x over previous
#include <cuda_runtime.h>
#include <stdint.h>

// Problem constants
#define B_   256
#define T_   256
#define C_   384
#define NH_  8
#define HD_  48
#define M_   (B_ * T_)        // 65536 rows
#define N1_  (3 * C_)         // 1152 qkv outputs
#define QKV_STRIDE 25165824   // B*T*C elements per q/k/v region

// Scratch (allocation-guard-safe: static __device__ globals)
__device__ float g_qkv[3ull * QKV_STRIDE];   // [3][B][NH][T][HD]
__device__ float g_att[(size_t)QKV_STRIDE];  // [B][T][C]

// ---------------------------------------------------------------------------
// tf32 helpers
// ---------------------------------------------------------------------------
__device__ __forceinline__ uint32_t f2tf(float f) {
    uint32_t u;
    asm("cvt.rna.tf32.f32 %0, %1;" : "=r"(u) : "f"(f));
    return u;
}

__device__ __forceinline__ void mma_tf32(
    float& c0, float& c1, float& c2, float& c3,
    uint32_t a0, uint32_t a1, uint32_t a2, uint32_t a3,
    uint32_t b0, uint32_t b1)
{
    asm volatile(
        "mma.sync.aligned.m16n8k8.row.col.f32.tf32.tf32.f32 "
        "{%0,%1,%2,%3}, {%4,%5,%6,%7}, {%8,%9}, {%0,%1,%2,%3};"
        : "+f"(c0), "+f"(c1), "+f"(c2), "+f"(c3)
        : "r"(a0), "r"(a1), "r"(a2), "r"(a3), "r"(b0), "r"(b1));
}

// ---------------------------------------------------------------------------
// R4 gemm_core (measured best: qkv 497us): 128x128 tile, BK=32, 256 thr =
// 8 warps (2m x 4n), warp 64x32.  Fragment-order smem, wide-LDS reads.
// ---------------------------------------------------------------------------
struct GemmFrag {
    float acc[4][4][4];   // [m-atom][n-atom][reg]
    int gid, ctg, wmB, wnB, lane;
};

__device__ __forceinline__ void gemm_core(
    const float* __restrict__ A, const float* __restrict__ W,
    int mBase, int nBase, uint32_t* As, uint32_t* Bs, GemmFrag& f)
{
    const int tid  = threadIdx.x;
    f.lane = tid & 31;
    const int warp = tid >> 5;
    f.gid = f.lane >> 2;
    f.ctg = f.lane & 3;
    f.wmB = (warp >> 2) * 64;
    f.wnB = (warp & 3) * 32;

#pragma unroll
    for (int i = 0; i < 4; ++i)
#pragma unroll
        for (int j = 0; j < 4; ++j)
#pragma unroll
            for (int r = 0; r < 4; ++r) f.acc[i][j][r] = 0.f;

    const int lrow    = tid >> 3;        // 0..31
    const int lcol    = (tid & 7) * 4;   // 0..28
    const int kb_w    = lcol >> 3;       // 0..3
    const int khalf_w = (lcol >> 2) & 1;

    for (int kt = 0; kt < 384; kt += 32) {
        float4 av[4], wv[4];
#pragma unroll
        for (int i = 0; i < 4; ++i) {
            av[i] = *(const float4*)(A + (size_t)(mBase + lrow + 32 * i) * 384 + kt + lcol);
            wv[i] = *(const float4*)(W + (size_t)(nBase + lrow + 32 * i) * 384 + kt + lcol);
        }
        __syncthreads();
#pragma unroll
        for (int i = 0; i < 4; ++i) {
            const int m   = lrow + 32 * i;
            const int am  = m >> 4;
            const int an  = m >> 3;
            const int gw4 = (m & 7) * 4;
            const int r8  = (m >> 3) & 1;
            const int aBase = (kb_w * 8 + am) * 128 + r8 + 2 * khalf_w;
            const int bBase = (kb_w * 16 + an) * 64 + khalf_w;
            const float va[4] = {av[i].x, av[i].y, av[i].z, av[i].w};
            const float vb[4] = {wv[i].x, wv[i].y, wv[i].z, wv[i].w};
#pragma unroll
            for (int c = 0; c < 4; ++c) {
                const int ls = (gw4 + c + kb_w) & 31;
                As[aBase + ls * 4] = f2tf(va[c]);
                Bs[bBase + ls * 2] = f2tf(vb[c]);
            }
        }
        __syncthreads();

#pragma unroll
        for (int kb = 0; kb < 4; ++kb) {
            const int lsw = (f.lane + kb) & 31;
            uint32_t a[4][4], b[4][2];
#pragma unroll
            for (int im = 0; im < 4; ++im) {
                const int am = (f.wmB >> 4) + im;
                const uint4 t4 = *(const uint4*)&As[(kb * 8 + am) * 128 + lsw * 4];
                a[im][0] = t4.x; a[im][1] = t4.y; a[im][2] = t4.z; a[im][3] = t4.w;
            }
#pragma unroll
            for (int jn = 0; jn < 4; ++jn) {
                const int an = (f.wnB >> 3) + jn;
                const uint2 t2 = *(const uint2*)&Bs[(kb * 16 + an) * 64 + lsw * 2];
                b[jn][0] = t2.x; b[jn][1] = t2.y;
            }
#pragma unroll
            for (int im = 0; im < 4; ++im)
#pragma unroll
                for (int jn = 0; jn < 4; ++jn)
                    mma_tf32(f.acc[im][jn][0], f.acc[im][jn][1],
                             f.acc[im][jn][2], f.acc[im][jn][3],
                             a[im][0], a[im][1], a[im][2], a[im][3],
                             b[jn][0], b[jn][1]);
        }
    }
}

// ---------------------------------------------------------------------------
// GEMM 1: qkv = x @ attn_w^T + attn_b, scattered head-major into g_qkv.
// ---------------------------------------------------------------------------
__global__ __launch_bounds__(256) void gemm_qkv_kernel(
    const float* __restrict__ A,
    const float* __restrict__ W,
    const float* __restrict__ bias)
{
    __shared__ uint32_t As[4096];
    __shared__ uint32_t Bs[4096];
    const int mBase = blockIdx.y * 128;
    const int nBase = blockIdx.x * 128;

    GemmFrag f;
    gemm_core(A, W, mBase, nBase, As, Bs, f);

#pragma unroll
    for (int im = 0; im < 4; ++im) {
#pragma unroll
        for (int jn = 0; jn < 4; ++jn) {
            const int col = nBase + f.wnB + jn * 8 + 2 * f.ctg;
            const float2 bi = *(const float2*)(bias + col);
            const int which = col / C_;
            const int c = col - which * C_;
            const int h = c / HD_;
            const int d = c - h * HD_;   // even; pair never straddles a head
#pragma unroll
            for (int half = 0; half < 2; ++half) {
                const int row = mBase + f.wmB + im * 16 + f.gid + half * 8;
                const int b = row >> 8;
                const int t = row & 255;
                float2 v;
                v.x = f.acc[im][jn][half * 2 + 0] + bi.x;
                v.y = f.acc[im][jn][half * 2 + 1] + bi.y;
                const size_t dst = (size_t)which * QKV_STRIDE
                                 + ((size_t)((b * NH_ + h) * T_ + t)) * HD_ + d;
                *(float2*)(g_qkv + dst) = v;
            }
        }
    }
}

// ---------------------------------------------------------------------------
// GEMM 2: out = g_att @ proj_w^T + proj_b.
// ---------------------------------------------------------------------------
__global__ __launch_bounds__(256) void gemm_proj_kernel(
    const float* __restrict__ W,
    const float* __restrict__ bias,
    float* __restrict__ out)
{
    __shared__ uint32_t As[4096];
    __shared__ uint32_t Bs[4096];
    const int mBase = blockIdx.y * 128;
    const int nBase = blockIdx.x * 128;

    GemmFrag f;
    gemm_core(g_att, W, mBase, nBase, As, Bs, f);

#pragma unroll
    for (int im = 0; im < 4; ++im) {
#pragma unroll
        for (int jn = 0; jn < 4; ++jn) {
            const int col = nBase + f.wnB + jn * 8 + 2 * f.ctg;
            const float2 bi = *(const float2*)(bias + col);
#pragma unroll
            for (int half = 0; half < 2; ++half) {
                const int row = mBase + f.wmB + im * 16 + f.gid + half * 8;
                float2 v;
                v.x = f.acc[im][jn][half * 2 + 0] + bi.x;
                v.y = f.acc[im][jn][half * 2 + 1] + bi.y;
                *(float2*)(out + (size_t)row * C_ + col) = v;
            }
        }
    }
}

// ---------------------------------------------------------------------------
// Flash attention, tf32 tensor cores (R6 verbatim; measured ~300us).
// ---------------------------------------------------------------------------
#define KSTR 52
#define VSTR 68

__global__ __launch_bounds__(256) void attn_kernel()
{
    __shared__ uint32_t sK[64 * KSTR];
    __shared__ uint32_t sVT[48 * VSTR];

    const int bh = blockIdx.x;
    const int qt = blockIdx.y;
    const int qb = qt * 128;
    const size_t base = (size_t)bh * (T_ * HD_);
    const float* Qg = g_qkv + base;
    const float* Kg = g_qkv + (size_t)QKV_STRIDE + base;
    const float* Vg = g_qkv + 2ull * QKV_STRIDE + base;

    const int tid  = threadIdx.x;
    const int lane = tid & 31;
    const int wid  = tid >> 5;
    const int gid  = lane >> 2;
    const int ctg  = lane & 3;

    const int r0  = wid * 16 + gid;
    const int r1  = r0 + 8;
    const int gr0 = qb + r0;
    const int gr1 = qb + r1;

    const float scale   = 0.14433756729740645f;   // 1/sqrt(48)
    const float NEG_INF = __int_as_float(0xff800000);

    uint32_t aq[6][4];
#pragma unroll
    for (int kb = 0; kb < 6; ++kb) {
        aq[kb][0] = f2tf(Qg[(size_t)gr0 * HD_ + kb * 8 + ctg]     * scale);
        aq[kb][1] = f2tf(Qg[(size_t)gr1 * HD_ + kb * 8 + ctg]     * scale);
        aq[kb][2] = f2tf(Qg[(size_t)gr0 * HD_ + kb * 8 + ctg + 4] * scale);
        aq[kb][3] = f2tf(Qg[(size_t)gr1 * HD_ + kb * 8 + ctg + 4] * scale);
    }

    float m0 = NEG_INF, m1 = NEG_INF, l0 = 0.f, l1 = 0.f;
    float o[6][4];
#pragma unroll
    for (int n = 0; n < 6; ++n)
#pragma unroll
        for (int r = 0; r < 4; ++r) o[n][r] = 0.f;

    const int npass = 2 * (qt + 1);
    for (int j = 0; j < npass; ++j) {
        const int jb = j * 64;
        __syncthreads();

#pragma unroll
        for (int i = 0; i < 3; ++i) {
            const int idx = tid + i * 256;
            const int r   = idx / 12;
            const int c4  = (idx % 12) * 4;
            const float4 kv = *(const float4*)(Kg + (size_t)(jb + r) * HD_ + c4);
            uint4 kt;
            kt.x = f2tf(kv.x); kt.y = f2tf(kv.y);
            kt.z = f2tf(kv.z); kt.w = f2tf(kv.w);
            *(uint4*)(sK + r * KSTR + c4) = kt;
            const float4 vv = *(const float4*)(Vg + (size_t)(jb + r) * HD_ + c4);
            sVT[(c4 + 0) * VSTR + r] = f2tf(vv.x);
            sVT[(c4 + 1) * VSTR + r] = f2tf(vv.y);
            sVT[(c4 + 2) * VSTR + r] = f2tf(vv.z);
            sVT[(c4 + 3) * VSTR + r] = f2tf(vv.w);
        }
        __syncthreads();

        if (jb > qb + wid * 16 + 15) continue;

        float s[8][4];
#pragma unroll
        for (int nb = 0; nb < 8; ++nb) {
            s[nb][0] = 0.f; s[nb][1] = 0.f; s[nb][2] = 0.f; s[nb][3] = 0.f;
#pragma unroll
            for (int kb = 0; kb < 6; ++kb) {
                const uint32_t b0 = sK[(nb * 8 + gid) * KSTR + kb * 8 + ctg];
                const uint32_t b1 = sK[(nb * 8 + gid) * KSTR + kb * 8 + ctg + 4];
                mma_tf32(s[nb][0], s[nb][1], s[nb][2], s[nb][3],
                         aq[kb][0], aq[kb][1], aq[kb][2], aq[kb][3], b0, b1);
            }
        }

        float tmax0 = NEG_INF, tmax1 = NEG_INF;
#pragma unroll
        for (int nb = 0; nb < 8; ++nb) {
            const int k0 = jb + nb * 8 + 2 * ctg;
            const int k1 = k0 + 1;
            if (k0 > gr0) s[nb][0] = NEG_INF;
            if (k1 > gr0) s[nb][1] = NEG_INF;
            if (k0 > gr1) s[nb][2] = NEG_INF;
            if (k1 > gr1) s[nb][3] = NEG_INF;
            tmax0 = fmaxf(tmax0, fmaxf(s[nb][0], s[nb][1]));
            tmax1 = fmaxf(tmax1, fmaxf(s[nb][2], s[nb][3]));
        }
        tmax0 = fmaxf(tmax0, __shfl_xor_sync(0xffffffffu, tmax0, 1));
        tmax0 = fmaxf(tmax0, __shfl_xor_sync(0xffffffffu, tmax0, 2));
        tmax1 = fmaxf(tmax1, __shfl_xor_sync(0xffffffffu, tmax1, 1));
        tmax1 = fmaxf(tmax1, __shfl_xor_sync(0xffffffffu, tmax1, 2));

        const float mn0 = fmaxf(m0, tmax0);
        const float mn1 = fmaxf(m1, tmax1);
        const float corr0 = __expf(m0 - mn0);
        const float corr1 = __expf(m1 - mn1);
        m0 = mn0; m1 = mn1;

        float ps0 = 0.f, ps1 = 0.f;
#pragma unroll
        for (int nb = 0; nb < 8; ++nb) {
            s[nb][0] = __expf(s[nb][0] - mn0);
            s[nb][1] = __expf(s[nb][1] - mn0);
            s[nb][2] = __expf(s[nb][2] - mn1);
            s[nb][3] = __expf(s[nb][3] - mn1);
            ps0 += s[nb][0] + s[nb][1];
            ps1 += s[nb][2] + s[nb][3];
        }
        ps0 += __shfl_xor_sync(0xffffffffu, ps0, 1);
        ps0 += __shfl_xor_sync(0xffffffffu, ps0, 2);
        ps1 += __shfl_xor_sync(0xffffffffu, ps1, 1);
        ps1 += __shfl_xor_sync(0xffffffffu, ps1, 2);
        l0 = l0 * corr0 + ps0;
        l1 = l1 * corr1 + ps1;

#pragma unroll
        for (int n = 0; n < 6; ++n) {
            o[n][0] *= corr0; o[n][1] *= corr0;
            o[n][2] *= corr1; o[n][3] *= corr1;
        }

        const int src0 = (lane & ~3) | (ctg >> 1);
        const int src1 = src0 + 2;
        const bool odd = ctg & 1;
#pragma unroll
        for (int kb = 0; kb < 8; ++kb) {
            const float v00 = __shfl_sync(0xffffffffu, s[kb][0], src0);
            const float v01 = __shfl_sync(0xffffffffu, s[kb][1], src0);
            const float v02 = __shfl_sync(0xffffffffu, s[kb][2], src0);
            const float v03 = __shfl_sync(0xffffffffu, s[kb][3], src0);
            const float v10 = __shfl_sync(0xffffffffu, s[kb][0], src1);
            const float v11 = __shfl_sync(0xffffffffu, s[kb][1], src1);
            const float v12 = __shfl_sync(0xffffffffu, s[kb][2], src1);
            const float v13 = __shfl_sync(0xffffffffu, s[kb][3], src1);
            uint32_t a0 = f2tf(odd ? v01 : v00);
            uint32_t a1 = f2tf(odd ? v03 : v02);
            uint32_t a2 = f2tf(odd ? v11 : v10);
            uint32_t a3 = f2tf(odd ? v13 : v12);
#pragma unroll
            for (int nb = 0; nb < 6; ++nb) {
                const uint32_t b0 = sVT[(nb * 8 + gid) * VSTR + kb * 8 + ctg];
                const uint32_t b1 = sVT[(nb * 8 + gid) * VSTR + kb * 8 + ctg + 4];
                mma_tf32(o[nb][0], o[nb][1], o[nb][2], o[nb][3],
                         a0, a1, a2, a3, b0, b1);
            }
        }
    }

    const float inv0 = 1.f / l0;
    const float inv1 = 1.f / l1;
    const int b = bh >> 3, h = bh & 7;
    float* dst0 = g_att + (size_t)(b * T_ + gr0) * C_ + h * HD_;
    float* dst1 = g_att + (size_t)(b * T_ + gr1) * C_ + h * HD_;
#pragma unroll
    for (int nb = 0; nb < 6; ++nb) {
        const int col = nb * 8 + 2 * ctg;
        float2 v0, v1;
        v0.x = o[nb][0] * inv0; v0.y = o[nb][1] * inv0;
        v1.x = o[nb][2] * inv1; v1.y = o[nb][3] * inv1;
        *(float2*)(dst0 + col) = v0;
        *(float2*)(dst1 + col) = v1;
    }
}

// ---------------------------------------------------------------------------
extern "C" void kernel_launch(void* const* d_in, const int* in_sizes, int n_in,
                              void* d_out, int out_size)
{
    const float* x      = (const float*)d_in[0];
    const float* attn_w = (const float*)d_in[1];
    const float* attn_b = (const float*)d_in[2];
    const float* proj_w = (const float*)d_in[3];
    const float* proj_b = (const float*)d_in[4];
    float* out = (float*)d_out;

    gemm_qkv_kernel<<<dim3(N1_ / 128, M_ / 128), 256>>>(x, attn_w, attn_b);
    attn_kernel<<<dim3(B_ * NH_, 2), 256>>>();
    gemm_proj_kernel<<<dim3(C_ / 128, M_ / 128), 256>>>(proj_w, proj_b, out);
}

// round 12
// speedup vs baseline: 1.2146x; 1.0951x over previous
#include <cuda_runtime.h>
#include <stdint.h>

// Problem constants
#define B_   256
#define T_   256
#define C_   384
#define NH_  8
#define HD_  48
#define M_   (B_ * T_)        // 65536 rows
#define N1_  (3 * C_)         // 1152 qkv outputs
#define QKV_STRIDE 25165824   // B*T*C elements per q/k/v region

// Scratch (allocation-guard-safe: static __device__ globals)
__device__ float g_qkv[3ull * QKV_STRIDE];   // [3][B][NH][T][HD]
__device__ float g_att[(size_t)QKV_STRIDE];  // [B][T][C]

// ---------------------------------------------------------------------------
// tf32 / cp.async helpers
// ---------------------------------------------------------------------------
__device__ __forceinline__ uint32_t f2tf(float f) {
    uint32_t u;
    asm("cvt.rna.tf32.f32 %0, %1;" : "=r"(u) : "f"(f));
    return u;
}

__device__ __forceinline__ void mma_tf32(
    float& c0, float& c1, float& c2, float& c3,
    uint32_t a0, uint32_t a1, uint32_t a2, uint32_t a3,
    uint32_t b0, uint32_t b1)
{
    asm volatile(
        "mma.sync.aligned.m16n8k8.row.col.f32.tf32.tf32.f32 "
        "{%0,%1,%2,%3}, {%4,%5,%6,%7}, {%8,%9}, {%0,%1,%2,%3};"
        : "+f"(c0), "+f"(c1), "+f"(c2), "+f"(c3)
        : "r"(a0), "r"(a1), "r"(a2), "r"(a3), "r"(b0), "r"(b1));
}

__device__ __forceinline__ void cpa16(uint32_t saddr, const void* g) {
    asm volatile("cp.async.ca.shared.global [%0], [%1], 16;"
                 :: "r"(saddr), "l"(g));
}
#define CP_COMMIT() asm volatile("cp.async.commit_group;")
#define CP_WAIT0()  asm volatile("cp.async.wait_group 0;")

struct GemmFrag {
    float acc[4][4][4];   // [m-atom][n-atom][reg]
    int gid, ctg, wmB, wnB, lane;
};

// ---------------------------------------------------------------------------
// CORE 1 (for qkv; measured 498us): R4 fragment-order core.
// 128x128 tile, BK=32, 256 thr = 8 warps (2m x 4n), warp 64x32.
// ---------------------------------------------------------------------------
__device__ __forceinline__ void gemm_core_frag(
    const float* __restrict__ A, const float* __restrict__ W,
    int mBase, int nBase, uint32_t* As, uint32_t* Bs, GemmFrag& f)
{
    const int tid  = threadIdx.x;
    f.lane = tid & 31;
    const int warp = tid >> 5;
    f.gid = f.lane >> 2;
    f.ctg = f.lane & 3;
    f.wmB = (warp >> 2) * 64;
    f.wnB = (warp & 3) * 32;

#pragma unroll
    for (int i = 0; i < 4; ++i)
#pragma unroll
        for (int j = 0; j < 4; ++j)
#pragma unroll
            for (int r = 0; r < 4; ++r) f.acc[i][j][r] = 0.f;

    const int lrow    = tid >> 3;        // 0..31
    const int lcol    = (tid & 7) * 4;   // 0..28
    const int kb_w    = lcol >> 3;       // 0..3
    const int khalf_w = (lcol >> 2) & 1;

    for (int kt = 0; kt < 384; kt += 32) {
        float4 av[4], wv[4];
#pragma unroll
        for (int i = 0; i < 4; ++i) {
            av[i] = *(const float4*)(A + (size_t)(mBase + lrow + 32 * i) * 384 + kt + lcol);
            wv[i] = *(const float4*)(W + (size_t)(nBase + lrow + 32 * i) * 384 + kt + lcol);
        }
        __syncthreads();
#pragma unroll
        for (int i = 0; i < 4; ++i) {
            const int m   = lrow + 32 * i;
            const int am  = m >> 4;
            const int an  = m >> 3;
            const int gw4 = (m & 7) * 4;
            const int r8  = (m >> 3) & 1;
            const int aBase = (kb_w * 8 + am) * 128 + r8 + 2 * khalf_w;
            const int bBase = (kb_w * 16 + an) * 64 + khalf_w;
            const float va[4] = {av[i].x, av[i].y, av[i].z, av[i].w};
            const float vb[4] = {wv[i].x, wv[i].y, wv[i].z, wv[i].w};
#pragma unroll
            for (int c = 0; c < 4; ++c) {
                const int ls = (gw4 + c + kb_w) & 31;
                As[aBase + ls * 4] = f2tf(va[c]);
                Bs[bBase + ls * 2] = f2tf(vb[c]);
            }
        }
        __syncthreads();

#pragma unroll
        for (int kb = 0; kb < 4; ++kb) {
            const int lsw = (f.lane + kb) & 31;
            uint32_t a[4][4], b[4][2];
#pragma unroll
            for (int im = 0; im < 4; ++im) {
                const int am = (f.wmB >> 4) + im;
                const uint4 t4 = *(const uint4*)&As[(kb * 8 + am) * 128 + lsw * 4];
                a[im][0] = t4.x; a[im][1] = t4.y; a[im][2] = t4.z; a[im][3] = t4.w;
            }
#pragma unroll
            for (int jn = 0; jn < 4; ++jn) {
                const int an = (f.wnB >> 3) + jn;
                const uint2 t2 = *(const uint2*)&Bs[(kb * 16 + an) * 64 + lsw * 2];
                b[jn][0] = t2.x; b[jn][1] = t2.y;
            }
#pragma unroll
            for (int im = 0; im < 4; ++im)
#pragma unroll
                for (int jn = 0; jn < 4; ++jn)
                    mma_tf32(f.acc[im][jn][0], f.acc[im][jn][1],
                             f.acc[im][jn][2], f.acc[im][jn][3],
                             a[im][0], a[im][1], a[im][2], a[im][3],
                             b[jn][0], b[jn][1]);
        }
    }
}

// ---------------------------------------------------------------------------
// CORE 2 (for proj; measured 64us): R5 cp.async double-buffered core.
// 128x128 tile, BK=16, m-major raw-fp32 smem (stride 20), cvt after LDS.
// ---------------------------------------------------------------------------
#define ASTR    20
#define BUF_ELT (128 * ASTR)   // 2560 floats per buffer

__device__ __forceinline__ void gemm_core_pipe(
    const float* __restrict__ A, const float* __restrict__ W,
    int mBase, int nBase, float* As, float* Bs, GemmFrag& f)
{
    const int tid  = threadIdx.x;
    const int lane = tid & 31;
    const int warp = tid >> 5;
    f.lane = lane;
    f.gid = lane >> 2;
    f.ctg = lane & 3;
    f.wmB = (warp >> 2) * 64;
    f.wnB = (warp & 3) * 32;

#pragma unroll
    for (int i = 0; i < 4; ++i)
#pragma unroll
        for (int j = 0; j < 4; ++j)
#pragma unroll
            for (int r = 0; r < 4; ++r) f.acc[i][j][r] = 0.f;

    const int lrow = tid >> 2;          // 0..63
    const int lkc  = (tid & 3) * 4;     // 0,4,8,12
    const uint32_t sA = (uint32_t)__cvta_generic_to_shared(As)
                      + (uint32_t)((lrow * ASTR + lkc) * 4);
    const uint32_t sB = (uint32_t)__cvta_generic_to_shared(Bs)
                      + (uint32_t)((lrow * ASTR + lkc) * 4);
    const float* gA0 = A + (size_t)(mBase + lrow) * 384 + lkc;
    const float* gA1 = gA0 + (size_t)64 * 384;
    const float* gW0 = W + (size_t)(nBase + lrow) * 384 + lkc;
    const float* gW1 = gW0 + (size_t)64 * 384;

    cpa16(sA,                 gA0);
    cpa16(sA + 64 * ASTR * 4, gA1);
    cpa16(sB,                 gW0);
    cpa16(sB + 64 * ASTR * 4, gW1);
    CP_COMMIT();

    const int a_m0 = f.wmB + f.gid;
    const int b_n0 = f.wnB + f.gid;

    for (int t = 0; t < 24; ++t) {
        CP_WAIT0();
        __syncthreads();

        if (t < 23) {
            const uint32_t off = (t & 1) ? 0u : (uint32_t)(BUF_ELT * 4);
            const int kt = (t + 1) * 16;
            cpa16(sA + off,                 gA0 + kt);
            cpa16(sA + off + 64 * ASTR * 4, gA1 + kt);
            cpa16(sB + off,                 gW0 + kt);
            cpa16(sB + off + 64 * ASTR * 4, gW1 + kt);
            CP_COMMIT();
        }

        const float* Ab = As + (t & 1) * BUF_ELT;
        const float* Bb = Bs + (t & 1) * BUF_ELT;

#pragma unroll
        for (int kb = 0; kb < 16; kb += 8) {
            uint32_t a[4][4], b[4][2];
#pragma unroll
            for (int im = 0; im < 4; ++im) {
                const int m0 = a_m0 + im * 16;
                a[im][0] = f2tf(Ab[(m0)     * ASTR + kb + f.ctg]);
                a[im][1] = f2tf(Ab[(m0 + 8) * ASTR + kb + f.ctg]);
                a[im][2] = f2tf(Ab[(m0)     * ASTR + kb + f.ctg + 4]);
                a[im][3] = f2tf(Ab[(m0 + 8) * ASTR + kb + f.ctg + 4]);
            }
#pragma unroll
            for (int jn = 0; jn < 4; ++jn) {
                const int n0 = b_n0 + jn * 8;
                b[jn][0] = f2tf(Bb[n0 * ASTR + kb + f.ctg]);
                b[jn][1] = f2tf(Bb[n0 * ASTR + kb + f.ctg + 4]);
            }
#pragma unroll
            for (int im = 0; im < 4; ++im)
#pragma unroll
                for (int jn = 0; jn < 4; ++jn)
                    mma_tf32(f.acc[im][jn][0], f.acc[im][jn][1],
                             f.acc[im][jn][2], f.acc[im][jn][3],
                             a[im][0], a[im][1], a[im][2], a[im][3],
                             b[jn][0], b[jn][1]);
        }
        __syncthreads();
    }
}

// ---------------------------------------------------------------------------
// GEMM 1: qkv = x @ attn_w^T + attn_b, scattered head-major into g_qkv.
// Uses CORE 1 (fragment-order, measured best for qkv).
// ---------------------------------------------------------------------------
__global__ __launch_bounds__(256) void gemm_qkv_kernel(
    const float* __restrict__ A,
    const float* __restrict__ W,
    const float* __restrict__ bias)
{
    __shared__ uint32_t As[4096];
    __shared__ uint32_t Bs[4096];
    const int mBase = blockIdx.y * 128;
    const int nBase = blockIdx.x * 128;

    GemmFrag f;
    gemm_core_frag(A, W, mBase, nBase, As, Bs, f);

#pragma unroll
    for (int im = 0; im < 4; ++im) {
#pragma unroll
        for (int jn = 0; jn < 4; ++jn) {
            const int col = nBase + f.wnB + jn * 8 + 2 * f.ctg;
            const float2 bi = *(const float2*)(bias + col);
            const int which = col / C_;
            const int c = col - which * C_;
            const int h = c / HD_;
            const int d = c - h * HD_;   // even; pair never straddles a head
#pragma unroll
            for (int half = 0; half < 2; ++half) {
                const int row = mBase + f.wmB + im * 16 + f.gid + half * 8;
                const int b = row >> 8;
                const int t = row & 255;
                float2 v;
                v.x = f.acc[im][jn][half * 2 + 0] + bi.x;
                v.y = f.acc[im][jn][half * 2 + 1] + bi.y;
                const size_t dst = (size_t)which * QKV_STRIDE
                                 + ((size_t)((b * NH_ + h) * T_ + t)) * HD_ + d;
                *(float2*)(g_qkv + dst) = v;
            }
        }
    }
}

// ---------------------------------------------------------------------------
// GEMM 2: out = g_att @ proj_w^T + proj_b.
// Uses CORE 2 (cp.async pipeline, measured best for proj).
// ---------------------------------------------------------------------------
__global__ __launch_bounds__(256) void gemm_proj_kernel(
    const float* __restrict__ W,
    const float* __restrict__ bias,
    float* __restrict__ out)
{
    __shared__ float As[2 * BUF_ELT];
    __shared__ float Bs[2 * BUF_ELT];
    const int mBase = blockIdx.y * 128;
    const int nBase = blockIdx.x * 128;

    GemmFrag f;
    gemm_core_pipe(g_att, W, mBase, nBase, As, Bs, f);

#pragma unroll
    for (int im = 0; im < 4; ++im) {
#pragma unroll
        for (int jn = 0; jn < 4; ++jn) {
            const int col = nBase + f.wnB + jn * 8 + 2 * f.ctg;
            const float2 bi = *(const float2*)(bias + col);
#pragma unroll
            for (int half = 0; half < 2; ++half) {
                const int row = mBase + f.wmB + im * 16 + f.gid + half * 8;
                float2 v;
                v.x = f.acc[im][jn][half * 2 + 0] + bi.x;
                v.y = f.acc[im][jn][half * 2 + 1] + bi.y;
                *(float2*)(out + (size_t)row * C_ + col) = v;
            }
        }
    }
}

// ---------------------------------------------------------------------------
// Flash attention, tf32 tensor cores (R6 verbatim; measured 395us).
// ---------------------------------------------------------------------------
#define KSTR 52
#define VSTR 68

__global__ __launch_bounds__(256) void attn_kernel()
{
    __shared__ uint32_t sK[64 * KSTR];
    __shared__ uint32_t sVT[48 * VSTR];

    const int bh = blockIdx.x;
    const int qt = blockIdx.y;
    const int qb = qt * 128;
    const size_t base = (size_t)bh * (T_ * HD_);
    const float* Qg = g_qkv + base;
    const float* Kg = g_qkv + (size_t)QKV_STRIDE + base;
    const float* Vg = g_qkv + 2ull * QKV_STRIDE + base;

    const int tid  = threadIdx.x;
    const int lane = tid & 31;
    const int wid  = tid >> 5;
    const int gid  = lane >> 2;
    const int ctg  = lane & 3;

    const int r0  = wid * 16 + gid;
    const int r1  = r0 + 8;
    const int gr0 = qb + r0;
    const int gr1 = qb + r1;

    const float scale   = 0.14433756729740645f;   // 1/sqrt(48)
    const float NEG_INF = __int_as_float(0xff800000);

    uint32_t aq[6][4];
#pragma unroll
    for (int kb = 0; kb < 6; ++kb) {
        aq[kb][0] = f2tf(Qg[(size_t)gr0 * HD_ + kb * 8 + ctg]     * scale);
        aq[kb][1] = f2tf(Qg[(size_t)gr1 * HD_ + kb * 8 + ctg]     * scale);
        aq[kb][2] = f2tf(Qg[(size_t)gr0 * HD_ + kb * 8 + ctg + 4] * scale);
        aq[kb][3] = f2tf(Qg[(size_t)gr1 * HD_ + kb * 8 + ctg + 4] * scale);
    }

    float m0 = NEG_INF, m1 = NEG_INF, l0 = 0.f, l1 = 0.f;
    float o[6][4];
#pragma unroll
    for (int n = 0; n < 6; ++n)
#pragma unroll
        for (int r = 0; r < 4; ++r) o[n][r] = 0.f;

    const int npass = 2 * (qt + 1);
    for (int j = 0; j < npass; ++j) {
        const int jb = j * 64;
        __syncthreads();

#pragma unroll
        for (int i = 0; i < 3; ++i) {
            const int idx = tid + i * 256;
            const int r   = idx / 12;
            const int c4  = (idx % 12) * 4;
            const float4 kv = *(const float4*)(Kg + (size_t)(jb + r) * HD_ + c4);
            uint4 kt;
            kt.x = f2tf(kv.x); kt.y = f2tf(kv.y);
            kt.z = f2tf(kv.z); kt.w = f2tf(kv.w);
            *(uint4*)(sK + r * KSTR + c4) = kt;
            const float4 vv = *(const float4*)(Vg + (size_t)(jb + r) * HD_ + c4);
            sVT[(c4 + 0) * VSTR + r] = f2tf(vv.x);
            sVT[(c4 + 1) * VSTR + r] = f2tf(vv.y);
            sVT[(c4 + 2) * VSTR + r] = f2tf(vv.z);
            sVT[(c4 + 3) * VSTR + r] = f2tf(vv.w);
        }
        __syncthreads();

        if (jb > qb + wid * 16 + 15) continue;

        float s[8][4];
#pragma unroll
        for (int nb = 0; nb < 8; ++nb) {
            s[nb][0] = 0.f; s[nb][1] = 0.f; s[nb][2] = 0.f; s[nb][3] = 0.f;
#pragma unroll
            for (int kb = 0; kb < 6; ++kb) {
                const uint32_t b0 = sK[(nb * 8 + gid) * KSTR + kb * 8 + ctg];
                const uint32_t b1 = sK[(nb * 8 + gid) * KSTR + kb * 8 + ctg + 4];
                mma_tf32(s[nb][0], s[nb][1], s[nb][2], s[nb][3],
                         aq[kb][0], aq[kb][1], aq[kb][2], aq[kb][3], b0, b1);
            }
        }

        float tmax0 = NEG_INF, tmax1 = NEG_INF;
#pragma unroll
        for (int nb = 0; nb < 8; ++nb) {
            const int k0 = jb + nb * 8 + 2 * ctg;
            const int k1 = k0 + 1;
            if (k0 > gr0) s[nb][0] = NEG_INF;
            if (k1 > gr0) s[nb][1] = NEG_INF;
            if (k0 > gr1) s[nb][2] = NEG_INF;
            if (k1 > gr1) s[nb][3] = NEG_INF;
            tmax0 = fmaxf(tmax0, fmaxf(s[nb][0], s[nb][1]));
            tmax1 = fmaxf(tmax1, fmaxf(s[nb][2], s[nb][3]));
        }
        tmax0 = fmaxf(tmax0, __shfl_xor_sync(0xffffffffu, tmax0, 1));
        tmax0 = fmaxf(tmax0, __shfl_xor_sync(0xffffffffu, tmax0, 2));
        tmax1 = fmaxf(tmax1, __shfl_xor_sync(0xffffffffu, tmax1, 1));
        tmax1 = fmaxf(tmax1, __shfl_xor_sync(0xffffffffu, tmax1, 2));

        const float mn0 = fmaxf(m0, tmax0);
        const float mn1 = fmaxf(m1, tmax1);
        const float corr0 = __expf(m0 - mn0);
        const float corr1 = __expf(m1 - mn1);
        m0 = mn0; m1 = mn1;

        float ps0 = 0.f, ps1 = 0.f;
#pragma unroll
        for (int nb = 0; nb < 8; ++nb) {
            s[nb][0] = __expf(s[nb][0] - mn0);
            s[nb][1] = __expf(s[nb][1] - mn0);
            s[nb][2] = __expf(s[nb][2] - mn1);
            s[nb][3] = __expf(s[nb][3] - mn1);
            ps0 += s[nb][0] + s[nb][1];
            ps1 += s[nb][2] + s[nb][3];
        }
        ps0 += __shfl_xor_sync(0xffffffffu, ps0, 1);
        ps0 += __shfl_xor_sync(0xffffffffu, ps0, 2);
        ps1 += __shfl_xor_sync(0xffffffffu, ps1, 1);
        ps1 += __shfl_xor_sync(0xffffffffu, ps1, 2);
        l0 = l0 * corr0 + ps0;
        l1 = l1 * corr1 + ps1;

#pragma unroll
        for (int n = 0; n < 6; ++n) {
            o[n][0] *= corr0; o[n][1] *= corr0;
            o[n][2] *= corr1; o[n][3] *= corr1;
        }

        const int src0 = (lane & ~3) | (ctg >> 1);
        const int src1 = src0 + 2;
        const bool odd = ctg & 1;
#pragma unroll
        for (int kb = 0; kb < 8; ++kb) {
            const float v00 = __shfl_sync(0xffffffffu, s[kb][0], src0);
            const float v01 = __shfl_sync(0xffffffffu, s[kb][1], src0);
            const float v02 = __shfl_sync(0xffffffffu, s[kb][2], src0);
            const float v03 = __shfl_sync(0xffffffffu, s[kb][3], src0);
            const float v10 = __shfl_sync(0xffffffffu, s[kb][0], src1);
            const float v11 = __shfl_sync(0xffffffffu, s[kb][1], src1);
            const float v12 = __shfl_sync(0xffffffffu, s[kb][2], src1);
            const float v13 = __shfl_sync(0xffffffffu, s[kb][3], src1);
            uint32_t a0 = f2tf(odd ? v01 : v00);
            uint32_t a1 = f2tf(odd ? v03 : v02);
            uint32_t a2 = f2tf(odd ? v11 : v10);
            uint32_t a3 = f2tf(odd ? v13 : v12);
#pragma unroll
            for (int nb = 0; nb < 6; ++nb) {
                const uint32_t b0 = sVT[(nb * 8 + gid) * VSTR + kb * 8 + ctg];
                const uint32_t b1 = sVT[(nb * 8 + gid) * VSTR + kb * 8 + ctg + 4];
                mma_tf32(o[nb][0], o[nb][1], o[nb][2], o[nb][3],
                         a0, a1, a2, a3, b0, b1);
            }
        }
    }

    const float inv0 = 1.f / l0;
    const float inv1 = 1.f / l1;
    const int b = bh >> 3, h = bh & 7;
    float* dst0 = g_att + (size_t)(b * T_ + gr0) * C_ + h * HD_;
    float* dst1 = g_att + (size_t)(b * T_ + gr1) * C_ + h * HD_;
#pragma unroll
    for (int nb = 0; nb < 6; ++nb) {
        const int col = nb * 8 + 2 * ctg;
        float2 v0, v1;
        v0.x = o[nb][0] * inv0; v0.y = o[nb][1] * inv0;
        v1.x = o[nb][2] * inv1; v1.y = o[nb][3] * inv1;
        *(float2*)(dst0 + col) = v0;
        *(float2*)(dst1 + col) = v1;
    }
}

// ---------------------------------------------------------------------------
extern "C" void kernel_launch(void* const* d_in, const int* in_sizes, int n_in,
                              void* d_out, int out_size)
{
    const float* x      = (const float*)d_in[0];
    const float* attn_w = (const float*)d_in[1];
    const float* attn_b = (const float*)d_in[2];
    const float* proj_w = (const float*)d_in[3];
    const float* proj_b = (const float*)d_in[4];
    float* out = (float*)d_out;

    gemm_qkv_kernel<<<dim3(N1_ / 128, M_ / 128), 256>>>(x, attn_w, attn_b);
    attn_kernel<<<dim3(B_ * NH_, 2), 256>>>();
    gemm_proj_kernel<<<dim3(C_ / 128, M_ / 128), 256>>>(proj_w, proj_b, out);
}

// round 14
// speedup vs baseline: 1.2795x; 1.0534x over previous
#include <cuda_runtime.h>
#include <stdint.h>

// Problem constants
#define B_   256
#define T_   256
#define C_   384
#define NH_  8
#define HD_  48
#define M_   (B_ * T_)        // 65536 rows
#define N1_  (3 * C_)         // 1152 qkv outputs
#define QKV_STRIDE 25165824   // B*T*C elements per q/k/v region

// Scratch (allocation-guard-safe: static __device__ globals)
__device__ float g_qkv[3ull * QKV_STRIDE];   // [3][B][NH][T][HD]
__device__ float g_att[(size_t)QKV_STRIDE];  // [B][T][C]

// ---------------------------------------------------------------------------
// tf32 / cp.async helpers
// ---------------------------------------------------------------------------
__device__ __forceinline__ uint32_t f2tf(float f) {
    uint32_t u;
    asm("cvt.rna.tf32.f32 %0, %1;" : "=r"(u) : "f"(f));
    return u;
}

__device__ __forceinline__ void mma_tf32(
    float& c0, float& c1, float& c2, float& c3,
    uint32_t a0, uint32_t a1, uint32_t a2, uint32_t a3,
    uint32_t b0, uint32_t b1)
{
    asm volatile(
        "mma.sync.aligned.m16n8k8.row.col.f32.tf32.tf32.f32 "
        "{%0,%1,%2,%3}, {%4,%5,%6,%7}, {%8,%9}, {%0,%1,%2,%3};"
        : "+f"(c0), "+f"(c1), "+f"(c2), "+f"(c3)
        : "r"(a0), "r"(a1), "r"(a2), "r"(a3), "r"(b0), "r"(b1));
}

__device__ __forceinline__ void cpa16(uint32_t saddr, const void* g) {
    asm volatile("cp.async.ca.shared.global [%0], [%1], 16;"
                 :: "r"(saddr), "l"(g));
}
#define CP_COMMIT() asm volatile("cp.async.commit_group;")
#define CP_WAIT0()  asm volatile("cp.async.wait_group 0;")

struct GemmFrag {
    float acc[4][4][4];   // [m-atom][n-atom][reg]
    int gid, ctg, wmB, wnB, lane;
};

// ---------------------------------------------------------------------------
// CORE 1 (qkv; measured 498us): R4 fragment-order core.
// 128x128 tile, BK=32, 256 thr = 8 warps (2m x 4n), warp 64x32.
// ---------------------------------------------------------------------------
__device__ __forceinline__ void gemm_core_frag(
    const float* __restrict__ A, const float* __restrict__ W,
    int mBase, int nBase, uint32_t* As, uint32_t* Bs, GemmFrag& f)
{
    const int tid  = threadIdx.x;
    f.lane = tid & 31;
    const int warp = tid >> 5;
    f.gid = f.lane >> 2;
    f.ctg = f.lane & 3;
    f.wmB = (warp >> 2) * 64;
    f.wnB = (warp & 3) * 32;

#pragma unroll
    for (int i = 0; i < 4; ++i)
#pragma unroll
        for (int j = 0; j < 4; ++j)
#pragma unroll
            for (int r = 0; r < 4; ++r) f.acc[i][j][r] = 0.f;

    const int lrow    = tid >> 3;        // 0..31
    const int lcol    = (tid & 7) * 4;   // 0..28
    const int kb_w    = lcol >> 3;       // 0..3
    const int khalf_w = (lcol >> 2) & 1;

    for (int kt = 0; kt < 384; kt += 32) {
        float4 av[4], wv[4];
#pragma unroll
        for (int i = 0; i < 4; ++i) {
            av[i] = *(const float4*)(A + (size_t)(mBase + lrow + 32 * i) * 384 + kt + lcol);
            wv[i] = *(const float4*)(W + (size_t)(nBase + lrow + 32 * i) * 384 + kt + lcol);
        }
        __syncthreads();
#pragma unroll
        for (int i = 0; i < 4; ++i) {
            const int m   = lrow + 32 * i;
            const int am  = m >> 4;
            const int an  = m >> 3;
            const int gw4 = (m & 7) * 4;
            const int r8  = (m >> 3) & 1;
            const int aBase = (kb_w * 8 + am) * 128 + r8 + 2 * khalf_w;
            const int bBase = (kb_w * 16 + an) * 64 + khalf_w;
            const float va[4] = {av[i].x, av[i].y, av[i].z, av[i].w};
            const float vb[4] = {wv[i].x, wv[i].y, wv[i].z, wv[i].w};
#pragma unroll
            for (int c = 0; c < 4; ++c) {
                const int ls = (gw4 + c + kb_w) & 31;
                As[aBase + ls * 4] = f2tf(va[c]);
                Bs[bBase + ls * 2] = f2tf(vb[c]);
            }
        }
        __syncthreads();

#pragma unroll
        for (int kb = 0; kb < 4; ++kb) {
            const int lsw = (f.lane + kb) & 31;
            uint32_t a[4][4], b[4][2];
#pragma unroll
            for (int im = 0; im < 4; ++im) {
                const int am = (f.wmB >> 4) + im;
                const uint4 t4 = *(const uint4*)&As[(kb * 8 + am) * 128 + lsw * 4];
                a[im][0] = t4.x; a[im][1] = t4.y; a[im][2] = t4.z; a[im][3] = t4.w;
            }
#pragma unroll
            for (int jn = 0; jn < 4; ++jn) {
                const int an = (f.wnB >> 3) + jn;
                const uint2 t2 = *(const uint2*)&Bs[(kb * 16 + an) * 64 + lsw * 2];
                b[jn][0] = t2.x; b[jn][1] = t2.y;
            }
#pragma unroll
            for (int im = 0; im < 4; ++im)
#pragma unroll
                for (int jn = 0; jn < 4; ++jn)
                    mma_tf32(f.acc[im][jn][0], f.acc[im][jn][1],
                             f.acc[im][jn][2], f.acc[im][jn][3],
                             a[im][0], a[im][1], a[im][2], a[im][3],
                             b[jn][0], b[jn][1]);
        }
    }
}

// ---------------------------------------------------------------------------
// CORE 2 (proj; measured ~64-110us): R5 cp.async double-buffered core.
// ---------------------------------------------------------------------------
#define ASTR    20
#define BUF_ELT (128 * ASTR)

__device__ __forceinline__ void gemm_core_pipe(
    const float* __restrict__ A, const float* __restrict__ W,
    int mBase, int nBase, float* As, float* Bs, GemmFrag& f)
{
    const int tid  = threadIdx.x;
    const int lane = tid & 31;
    const int warp = tid >> 5;
    f.lane = lane;
    f.gid = lane >> 2;
    f.ctg = lane & 3;
    f.wmB = (warp >> 2) * 64;
    f.wnB = (warp & 3) * 32;

#pragma unroll
    for (int i = 0; i < 4; ++i)
#pragma unroll
        for (int j = 0; j < 4; ++j)
#pragma unroll
            for (int r = 0; r < 4; ++r) f.acc[i][j][r] = 0.f;

    const int lrow = tid >> 2;
    const int lkc  = (tid & 3) * 4;
    const uint32_t sA = (uint32_t)__cvta_generic_to_shared(As)
                      + (uint32_t)((lrow * ASTR + lkc) * 4);
    const uint32_t sB = (uint32_t)__cvta_generic_to_shared(Bs)
                      + (uint32_t)((lrow * ASTR + lkc) * 4);
    const float* gA0 = A + (size_t)(mBase + lrow) * 384 + lkc;
    const float* gA1 = gA0 + (size_t)64 * 384;
    const float* gW0 = W + (size_t)(nBase + lrow) * 384 + lkc;
    const float* gW1 = gW0 + (size_t)64 * 384;

    cpa16(sA,                 gA0);
    cpa16(sA + 64 * ASTR * 4, gA1);
    cpa16(sB,                 gW0);
    cpa16(sB + 64 * ASTR * 4, gW1);
    CP_COMMIT();

    const int a_m0 = f.wmB + f.gid;
    const int b_n0 = f.wnB + f.gid;

    for (int t = 0; t < 24; ++t) {
        CP_WAIT0();
        __syncthreads();

        if (t < 23) {
            const uint32_t off = (t & 1) ? 0u : (uint32_t)(BUF_ELT * 4);
            const int kt = (t + 1) * 16;
            cpa16(sA + off,                 gA0 + kt);
            cpa16(sA + off + 64 * ASTR * 4, gA1 + kt);
            cpa16(sB + off,                 gW0 + kt);
            cpa16(sB + off + 64 * ASTR * 4, gW1 + kt);
            CP_COMMIT();
        }

        const float* Ab = As + (t & 1) * BUF_ELT;
        const float* Bb = Bs + (t & 1) * BUF_ELT;

#pragma unroll
        for (int kb = 0; kb < 16; kb += 8) {
            uint32_t a[4][4], b[4][2];
#pragma unroll
            for (int im = 0; im < 4; ++im) {
                const int m0 = a_m0 + im * 16;
                a[im][0] = f2tf(Ab[(m0)     * ASTR + kb + f.ctg]);
                a[im][1] = f2tf(Ab[(m0 + 8) * ASTR + kb + f.ctg]);
                a[im][2] = f2tf(Ab[(m0)     * ASTR + kb + f.ctg + 4]);
                a[im][3] = f2tf(Ab[(m0 + 8) * ASTR + kb + f.ctg + 4]);
            }
#pragma unroll
            for (int jn = 0; jn < 4; ++jn) {
                const int n0 = b_n0 + jn * 8;
                b[jn][0] = f2tf(Bb[n0 * ASTR + kb + f.ctg]);
                b[jn][1] = f2tf(Bb[n0 * ASTR + kb + f.ctg + 4]);
            }
#pragma unroll
            for (int im = 0; im < 4; ++im)
#pragma unroll
                for (int jn = 0; jn < 4; ++jn)
                    mma_tf32(f.acc[im][jn][0], f.acc[im][jn][1],
                             f.acc[im][jn][2], f.acc[im][jn][3],
                             a[im][0], a[im][1], a[im][2], a[im][3],
                             b[jn][0], b[jn][1]);
        }
        __syncthreads();
    }
}

// ---------------------------------------------------------------------------
// GEMM 1: qkv = x @ attn_w^T + attn_b, scattered head-major into g_qkv.
// ---------------------------------------------------------------------------
__global__ __launch_bounds__(256) void gemm_qkv_kernel(
    const float* __restrict__ A,
    const float* __restrict__ W,
    const float* __restrict__ bias)
{
    __shared__ uint32_t As[4096];
    __shared__ uint32_t Bs[4096];
    const int mBase = blockIdx.y * 128;
    const int nBase = blockIdx.x * 128;

    GemmFrag f;
    gemm_core_frag(A, W, mBase, nBase, As, Bs, f);

#pragma unroll
    for (int im = 0; im < 4; ++im) {
#pragma unroll
        for (int jn = 0; jn < 4; ++jn) {
            const int col = nBase + f.wnB + jn * 8 + 2 * f.ctg;
            const float2 bi = *(const float2*)(bias + col);
            const int which = col / C_;
            const int c = col - which * C_;
            const int h = c / HD_;
            const int d = c - h * HD_;   // even; pair never straddles a head
#pragma unroll
            for (int half = 0; half < 2; ++half) {
                const int row = mBase + f.wmB + im * 16 + f.gid + half * 8;
                const int b = row >> 8;
                const int t = row & 255;
                float2 v;
                v.x = f.acc[im][jn][half * 2 + 0] + bi.x;
                v.y = f.acc[im][jn][half * 2 + 1] + bi.y;
                const size_t dst = (size_t)which * QKV_STRIDE
                                 + ((size_t)((b * NH_ + h) * T_ + t)) * HD_ + d;
                *(float2*)(g_qkv + dst) = v;
            }
        }
    }
}

// ---------------------------------------------------------------------------
// GEMM 2: out = g_att @ proj_w^T + proj_b.
// ---------------------------------------------------------------------------
__global__ __launch_bounds__(256) void gemm_proj_kernel(
    const float* __restrict__ W,
    const float* __restrict__ bias,
    float* __restrict__ out)
{
    __shared__ float As[2 * BUF_ELT];
    __shared__ float Bs[2 * BUF_ELT];
    const int mBase = blockIdx.y * 128;
    const int nBase = blockIdx.x * 128;

    GemmFrag f;
    gemm_core_pipe(g_att, W, mBase, nBase, As, Bs, f);

#pragma unroll
    for (int im = 0; im < 4; ++im) {
#pragma unroll
        for (int jn = 0; jn < 4; ++jn) {
            const int col = nBase + f.wnB + jn * 8 + 2 * f.ctg;
            const float2 bi = *(const float2*)(bias + col);
#pragma unroll
            for (int half = 0; half < 2; ++half) {
                const int row = mBase + f.wmB + im * 16 + f.gid + half * 8;
                float2 v;
                v.x = f.acc[im][jn][half * 2 + 0] + bi.x;
                v.y = f.acc[im][jn][half * 2 + 1] + bi.y;
                *(float2*)(out + (size_t)row * C_ + col) = v;
            }
        }
    }
}

// ---------------------------------------------------------------------------
// Flash attention, tf32 tensor cores.  R6 base + two exact optimizations:
//  (a) register prefetch of next K/V tile (hides LDG under compute)
//  (b) warp-uniform fine-grained causal skip at 8-key atom granularity
//      (skipped atoms contribute exactly NEG_INF / 0.0 -> bit-identical)
// ---------------------------------------------------------------------------
#define KSTR 52
#define VSTR 68

__global__ __launch_bounds__(256, 2) void attn_kernel()
{
    __shared__ uint32_t sK[64 * KSTR];
    __shared__ uint32_t sVT[48 * VSTR];

    const int bh = blockIdx.x;
    const int qt = blockIdx.y;
    const int qb = qt * 128;
    const size_t base = (size_t)bh * (T_ * HD_);
    const float* Qg = g_qkv + base;
    const float* Kg = g_qkv + (size_t)QKV_STRIDE + base;
    const float* Vg = g_qkv + 2ull * QKV_STRIDE + base;

    const int tid  = threadIdx.x;
    const int lane = tid & 31;
    const int wid  = tid >> 5;
    const int gid  = lane >> 2;
    const int ctg  = lane & 3;

    const int r0  = wid * 16 + gid;
    const int r1  = r0 + 8;
    const int gr0 = qb + r0;
    const int gr1 = qb + r1;
    const int wtop = qb + wid * 16 + 15;    // last row owned by this warp

    const float scale   = 0.14433756729740645f;   // 1/sqrt(48)
    const float NEG_INF = __int_as_float(0xff800000);

    uint32_t aq[6][4];
#pragma unroll
    for (int kb = 0; kb < 6; ++kb) {
        aq[kb][0] = f2tf(Qg[(size_t)gr0 * HD_ + kb * 8 + ctg]     * scale);
        aq[kb][1] = f2tf(Qg[(size_t)gr1 * HD_ + kb * 8 + ctg]     * scale);
        aq[kb][2] = f2tf(Qg[(size_t)gr0 * HD_ + kb * 8 + ctg + 4] * scale);
        aq[kb][3] = f2tf(Qg[(size_t)gr1 * HD_ + kb * 8 + ctg + 4] * scale);
    }

    // staging address map (same for all tiles)
    int srow[3], scol[3];
#pragma unroll
    for (int i = 0; i < 3; ++i) {
        const int idx = tid + i * 256;
        srow[i] = idx / 12;
        scol[i] = (idx % 12) * 4;
    }

    float m0 = NEG_INF, m1 = NEG_INF, l0 = 0.f, l1 = 0.f;
    float o[6][4];
#pragma unroll
    for (int n = 0; n < 6; ++n)
#pragma unroll
        for (int r = 0; r < 4; ++r) o[n][r] = 0.f;

    const int npass = 2 * (qt + 1);

    // preload tile 0 into registers
    float4 kreg[3], vreg[3];
#pragma unroll
    for (int i = 0; i < 3; ++i) {
        kreg[i] = *(const float4*)(Kg + (size_t)srow[i] * HD_ + scol[i]);
        vreg[i] = *(const float4*)(Vg + (size_t)srow[i] * HD_ + scol[i]);
    }

    for (int j = 0; j < npass; ++j) {
        const int jb = j * 64;
        __syncthreads();   // previous tile fully consumed

        // stage current tile from registers (convert at store)
#pragma unroll
        for (int i = 0; i < 3; ++i) {
            const int r  = srow[i];
            const int c4 = scol[i];
            uint4 kt;
            kt.x = f2tf(kreg[i].x); kt.y = f2tf(kreg[i].y);
            kt.z = f2tf(kreg[i].z); kt.w = f2tf(kreg[i].w);
            *(uint4*)(sK + r * KSTR + c4) = kt;
            sVT[(c4 + 0) * VSTR + r] = f2tf(vreg[i].x);
            sVT[(c4 + 1) * VSTR + r] = f2tf(vreg[i].y);
            sVT[(c4 + 2) * VSTR + r] = f2tf(vreg[i].z);
            sVT[(c4 + 3) * VSTR + r] = f2tf(vreg[i].w);
        }
        __syncthreads();

        // prefetch next tile (hidden under this tile's compute)
        if (j + 1 < npass) {
            const int jn2 = (j + 1) * 64;
#pragma unroll
            for (int i = 0; i < 3; ++i) {
                kreg[i] = *(const float4*)(Kg + (size_t)(jn2 + srow[i]) * HD_ + scol[i]);
                vreg[i] = *(const float4*)(Vg + (size_t)(jn2 + srow[i]) * HD_ + scol[i]);
            }
        }

        if (jb > wtop) continue;                       // whole tile masked
        const int nbmax = min(8, ((wtop - jb) >> 3) + 1);   // valid 8-key atoms

        // --- S = Q K^T over valid atoms only ---
        float s[8][4];
#pragma unroll
        for (int nb = 0; nb < 8; ++nb) {
            if (nb < nbmax) {
                s[nb][0] = 0.f; s[nb][1] = 0.f; s[nb][2] = 0.f; s[nb][3] = 0.f;
#pragma unroll
                for (int kb = 0; kb < 6; ++kb) {
                    const uint32_t b0 = sK[(nb * 8 + gid) * KSTR + kb * 8 + ctg];
                    const uint32_t b1 = sK[(nb * 8 + gid) * KSTR + kb * 8 + ctg + 4];
                    mma_tf32(s[nb][0], s[nb][1], s[nb][2], s[nb][3],
                             aq[kb][0], aq[kb][1], aq[kb][2], aq[kb][3], b0, b1);
                }
            } else {
                s[nb][0] = NEG_INF; s[nb][1] = NEG_INF;
                s[nb][2] = NEG_INF; s[nb][3] = NEG_INF;
            }
        }

        // --- mask + online softmax (only valid atoms feed max/exp) ---
        float tmax0 = NEG_INF, tmax1 = NEG_INF;
#pragma unroll
        for (int nb = 0; nb < 8; ++nb) {
            if (nb >= nbmax) continue;
            const int k0 = jb + nb * 8 + 2 * ctg;
            const int k1 = k0 + 1;
            if (k0 > gr0) s[nb][0] = NEG_INF;
            if (k1 > gr0) s[nb][1] = NEG_INF;
            if (k0 > gr1) s[nb][2] = NEG_INF;
            if (k1 > gr1) s[nb][3] = NEG_INF;
            tmax0 = fmaxf(tmax0, fmaxf(s[nb][0], s[nb][1]));
            tmax1 = fmaxf(tmax1, fmaxf(s[nb][2], s[nb][3]));
        }
        tmax0 = fmaxf(tmax0, __shfl_xor_sync(0xffffffffu, tmax0, 1));
        tmax0 = fmaxf(tmax0, __shfl_xor_sync(0xffffffffu, tmax0, 2));
        tmax1 = fmaxf(tmax1, __shfl_xor_sync(0xffffffffu, tmax1, 1));
        tmax1 = fmaxf(tmax1, __shfl_xor_sync(0xffffffffu, tmax1, 2));

        const float mn0 = fmaxf(m0, tmax0);
        const float mn1 = fmaxf(m1, tmax1);
        const float corr0 = __expf(m0 - mn0);
        const float corr1 = __expf(m1 - mn1);
        m0 = mn0; m1 = mn1;

        float ps0 = 0.f, ps1 = 0.f;
#pragma unroll
        for (int nb = 0; nb < 8; ++nb) {
            if (nb >= nbmax) continue;      // exp(NEG_INF)=0 adds exactly 0
            s[nb][0] = __expf(s[nb][0] - mn0);
            s[nb][1] = __expf(s[nb][1] - mn0);
            s[nb][2] = __expf(s[nb][2] - mn1);
            s[nb][3] = __expf(s[nb][3] - mn1);
            ps0 += s[nb][0] + s[nb][1];
            ps1 += s[nb][2] + s[nb][3];
        }
        ps0 += __shfl_xor_sync(0xffffffffu, ps0, 1);
        ps0 += __shfl_xor_sync(0xffffffffu, ps0, 2);
        ps1 += __shfl_xor_sync(0xffffffffu, ps1, 1);
        ps1 += __shfl_xor_sync(0xffffffffu, ps1, 2);
        l0 = l0 * corr0 + ps0;
        l1 = l1 * corr1 + ps1;

#pragma unroll
        for (int n = 0; n < 6; ++n) {
            o[n][0] *= corr0; o[n][1] *= corr0;
            o[n][2] *= corr1; o[n][3] *= corr1;
        }

        // --- PV over valid atoms only (skipped atoms have P == 0 exactly) ---
        const int src0 = (lane & ~3) | (ctg >> 1);
        const int src1 = src0 + 2;
        const bool odd = ctg & 1;
#pragma unroll
        for (int kb = 0; kb < 8; ++kb) {
            if (kb >= nbmax) continue;
            const float v00 = __shfl_sync(0xffffffffu, s[kb][0], src0);
            const float v01 = __shfl_sync(0xffffffffu, s[kb][1], src0);
            const float v02 = __shfl_sync(0xffffffffu, s[kb][2], src0);
            const float v03 = __shfl_sync(0xffffffffu, s[kb][3], src0);
            const float v10 = __shfl_sync(0xffffffffu, s[kb][0], src1);
            const float v11 = __shfl_sync(0xffffffffu, s[kb][1], src1);
            const float v12 = __shfl_sync(0xffffffffu, s[kb][2], src1);
            const float v13 = __shfl_sync(0xffffffffu, s[kb][3], src1);
            uint32_t a0 = f2tf(odd ? v01 : v00);
            uint32_t a1 = f2tf(odd ? v03 : v02);
            uint32_t a2 = f2tf(odd ? v11 : v10);
            uint32_t a3 = f2tf(odd ? v13 : v12);
#pragma unroll
            for (int nb = 0; nb < 6; ++nb) {
                const uint32_t b0 = sVT[(nb * 8 + gid) * VSTR + kb * 8 + ctg];
                const uint32_t b1 = sVT[(nb * 8 + gid) * VSTR + kb * 8 + ctg + 4];
                mma_tf32(o[nb][0], o[nb][1], o[nb][2], o[nb][3],
                         a0, a1, a2, a3, b0, b1);
            }
        }
    }

    const float inv0 = 1.f / l0;
    const float inv1 = 1.f / l1;
    const int b = bh >> 3, h = bh & 7;
    float* dst0 = g_att + (size_t)(b * T_ + gr0) * C_ + h * HD_;
    float* dst1 = g_att + (size_t)(b * T_ + gr1) * C_ + h * HD_;
#pragma unroll
    for (int nb = 0; nb < 6; ++nb) {
        const int col = nb * 8 + 2 * ctg;
        float2 v0, v1;
        v0.x = o[nb][0] * inv0; v0.y = o[nb][1] * inv0;
        v1.x = o[nb][2] * inv1; v1.y = o[nb][3] * inv1;
        *(float2*)(dst0 + col) = v0;
        *(float2*)(dst1 + col) = v1;
    }
}

// ---------------------------------------------------------------------------
extern "C" void kernel_launch(void* const* d_in, const int* in_sizes, int n_in,
                              void* d_out, int out_size)
{
    const float* x      = (const float*)d_in[0];
    const float* attn_w = (const float*)d_in[1];
    const float* attn_b = (const float*)d_in[2];
    const float* proj_w = (const float*)d_in[3];
    const float* proj_b = (const float*)d_in[4];
    float* out = (float*)d_out;

    gemm_qkv_kernel<<<dim3(N1_ / 128, M_ / 128), 256>>>(x, attn_w, attn_b);
    attn_kernel<<<dim3(B_ * NH_, 2), 256>>>();
    gemm_proj_kernel<<<dim3(C_ / 128, M_ / 128), 256>>>(proj_w, proj_b, out);
}

// round 17
// speedup vs baseline: 1.2900x; 1.0082x over previous
#include <cuda_runtime.h>
#include <stdint.h>

// R15 experiment, resubmission #2 (bytes refreshed to rule out content-keyed
// broker-cache pathology; semantics identical to the R15/R16 submissions).
// Problem constants
#define B_   256
#define T_   256
#define C_   384
#define NH_  8
#define HD_  48
#define M_   (B_ * T_)        // 65536 rows
#define N1_  (3 * C_)         // 1152 qkv outputs
#define QKV_STRIDE 25165824   // B*T*C elements per q/k/v region

// Scratch (allocation-guard-safe: static __device__ globals)
__device__ float g_qkv[3ull * QKV_STRIDE];   // [3][B][NH][T][HD]
__device__ float g_att[(size_t)QKV_STRIDE];  // [B][T][C]

// ---------------------------------------------------------------------------
// tf32 / cp.async helpers
// ---------------------------------------------------------------------------
__device__ __forceinline__ uint32_t cvt_tf32(float f) {
    uint32_t u;
    asm("cvt.rna.tf32.f32 %0, %1;" : "=r"(u) : "f"(f));
    return u;
}
#define f2tf cvt_tf32

__device__ __forceinline__ void mma_tf32(
    float& c0, float& c1, float& c2, float& c3,
    uint32_t a0, uint32_t a1, uint32_t a2, uint32_t a3,
    uint32_t b0, uint32_t b1)
{
    asm volatile(
        "mma.sync.aligned.m16n8k8.row.col.f32.tf32.tf32.f32 "
        "{%0,%1,%2,%3}, {%4,%5,%6,%7}, {%8,%9}, {%0,%1,%2,%3};"
        : "+f"(c0), "+f"(c1), "+f"(c2), "+f"(c3)
        : "r"(a0), "r"(a1), "r"(a2), "r"(a3), "r"(b0), "r"(b1));
}

__device__ __forceinline__ void cpa16(uint32_t saddr, const void* g) {
    asm volatile("cp.async.ca.shared.global [%0], [%1], 16;"
                 :: "r"(saddr), "l"(g));
}
#define CP_COMMIT() asm volatile("cp.async.commit_group;")
#define CP_WAIT0()  asm volatile("cp.async.wait_group 0;")

struct GemmFrag {
    float acc[4][4][4];   // [m-atom][n-atom][reg]
    int gid, ctg, wmB, wnB, lane;
};

// ---------------------------------------------------------------------------
// CORE 1 (qkv): R4 fragment-order core with the LDG issue point moved ahead
// of compute(t) into the dead av/wv registers (register-neutral pipelining).
// Layout, barriers, and accumulation order identical to the R4/R14 core.
// ---------------------------------------------------------------------------
__device__ __forceinline__ void gemm_core_frag(
    const float* __restrict__ A, const float* __restrict__ W,
    int mBase, int nBase, uint32_t* As, uint32_t* Bs, GemmFrag& f)
{
    const int tid  = threadIdx.x;
    f.lane = tid & 31;
    const int warp = tid >> 5;
    f.gid = f.lane >> 2;
    f.ctg = f.lane & 3;
    f.wmB = (warp >> 2) * 64;
    f.wnB = (warp & 3) * 32;

#pragma unroll
    for (int i = 0; i < 4; ++i)
#pragma unroll
        for (int j = 0; j < 4; ++j)
#pragma unroll
            for (int r = 0; r < 4; ++r) f.acc[i][j][r] = 0.f;

    const int lrow    = tid >> 3;        // 0..31
    const int lcol    = (tid & 7) * 4;   // 0..28
    const int kb_w    = lcol >> 3;       // 0..3
    const int khalf_w = (lcol >> 2) & 1;

    float4 av[4], wv[4];
#pragma unroll
    for (int i = 0; i < 4; ++i) {
        av[i] = *(const float4*)(A + (size_t)(mBase + lrow + 32 * i) * 384 + lcol);
        wv[i] = *(const float4*)(W + (size_t)(nBase + lrow + 32 * i) * 384 + lcol);
    }

    for (int t = 0; t < 12; ++t) {
        __syncthreads();   // previous tile's readers done
#pragma unroll
        for (int i = 0; i < 4; ++i) {
            const int m   = lrow + 32 * i;
            const int am  = m >> 4;
            const int an  = m >> 3;
            const int gw4 = (m & 7) * 4;
            const int r8  = (m >> 3) & 1;
            const int aBase = (kb_w * 8 + am) * 128 + r8 + 2 * khalf_w;
            const int bBase = (kb_w * 16 + an) * 64 + khalf_w;
            const float va[4] = {av[i].x, av[i].y, av[i].z, av[i].w};
            const float vb[4] = {wv[i].x, wv[i].y, wv[i].z, wv[i].w};
#pragma unroll
            for (int c = 0; c < 4; ++c) {
                const int ls = (gw4 + c + kb_w) & 31;
                As[aBase + ls * 4] = f2tf(va[c]);
                Bs[bBase + ls * 2] = f2tf(vb[c]);
            }
        }
        __syncthreads();

        if (t < 11) {      // prefetch tile t+1 — latency drains under compute(t)
            const int kt = (t + 1) * 32;
#pragma unroll
            for (int i = 0; i < 4; ++i) {
                av[i] = *(const float4*)(A + (size_t)(mBase + lrow + 32 * i) * 384 + kt + lcol);
                wv[i] = *(const float4*)(W + (size_t)(nBase + lrow + 32 * i) * 384 + kt + lcol);
            }
        }

#pragma unroll
        for (int kb = 0; kb < 4; ++kb) {
            const int lsw = (f.lane + kb) & 31;
            uint32_t a[4][4], b[4][2];
#pragma unroll
            for (int im = 0; im < 4; ++im) {
                const int am = (f.wmB >> 4) + im;
                const uint4 t4 = *(const uint4*)&As[(kb * 8 + am) * 128 + lsw * 4];
                a[im][0] = t4.x; a[im][1] = t4.y; a[im][2] = t4.z; a[im][3] = t4.w;
            }
#pragma unroll
            for (int jn = 0; jn < 4; ++jn) {
                const int an = (f.wnB >> 3) + jn;
                const uint2 t2 = *(const uint2*)&Bs[(kb * 16 + an) * 64 + lsw * 2];
                b[jn][0] = t2.x; b[jn][1] = t2.y;
            }
#pragma unroll
            for (int im = 0; im < 4; ++im)
#pragma unroll
                for (int jn = 0; jn < 4; ++jn)
                    mma_tf32(f.acc[im][jn][0], f.acc[im][jn][1],
                             f.acc[im][jn][2], f.acc[im][jn][3],
                             a[im][0], a[im][1], a[im][2], a[im][3],
                             b[jn][0], b[jn][1]);
        }
    }
}

// ---------------------------------------------------------------------------
// CORE 2 (proj): R5 cp.async double-buffered core (verbatim).
// ---------------------------------------------------------------------------
#define ASTR    20
#define BUF_ELT (128 * ASTR)

__device__ __forceinline__ void gemm_core_pipe(
    const float* __restrict__ A, const float* __restrict__ W,
    int mBase, int nBase, float* As, float* Bs, GemmFrag& f)
{
    const int tid  = threadIdx.x;
    const int lane = tid & 31;
    const int warp = tid >> 5;
    f.lane = lane;
    f.gid = lane >> 2;
    f.ctg = lane & 3;
    f.wmB = (warp >> 2) * 64;
    f.wnB = (warp & 3) * 32;

#pragma unroll
    for (int i = 0; i < 4; ++i)
#pragma unroll
        for (int j = 0; j < 4; ++j)
#pragma unroll
            for (int r = 0; r < 4; ++r) f.acc[i][j][r] = 0.f;

    const int lrow = tid >> 2;
    const int lkc  = (tid & 3) * 4;
    const uint32_t sA = (uint32_t)__cvta_generic_to_shared(As)
                      + (uint32_t)((lrow * ASTR + lkc) * 4);
    const uint32_t sB = (uint32_t)__cvta_generic_to_shared(Bs)
                      + (uint32_t)((lrow * ASTR + lkc) * 4);
    const float* gA0 = A + (size_t)(mBase + lrow) * 384 + lkc;
    const float* gA1 = gA0 + (size_t)64 * 384;
    const float* gW0 = W + (size_t)(nBase + lrow) * 384 + lkc;
    const float* gW1 = gW0 + (size_t)64 * 384;

    cpa16(sA,                 gA0);
    cpa16(sA + 64 * ASTR * 4, gA1);
    cpa16(sB,                 gW0);
    cpa16(sB + 64 * ASTR * 4, gW1);
    CP_COMMIT();

    const int a_m0 = f.wmB + f.gid;
    const int b_n0 = f.wnB + f.gid;

    for (int t = 0; t < 24; ++t) {
        CP_WAIT0();
        __syncthreads();

        if (t < 23) {
            const uint32_t off = (t & 1) ? 0u : (uint32_t)(BUF_ELT * 4);
            const int kt = (t + 1) * 16;
            cpa16(sA + off,                 gA0 + kt);
            cpa16(sA + off + 64 * ASTR * 4, gA1 + kt);
            cpa16(sB + off,                 gW0 + kt);
            cpa16(sB + off + 64 * ASTR * 4, gW1 + kt);
            CP_COMMIT();
        }

        const float* Ab = As + (t & 1) * BUF_ELT;
        const float* Bb = Bs + (t & 1) * BUF_ELT;

#pragma unroll
        for (int kb = 0; kb < 16; kb += 8) {
            uint32_t a[4][4], b[4][2];
#pragma unroll
            for (int im = 0; im < 4; ++im) {
                const int m0 = a_m0 + im * 16;
                a[im][0] = f2tf(Ab[(m0)     * ASTR + kb + f.ctg]);
                a[im][1] = f2tf(Ab[(m0 + 8) * ASTR + kb + f.ctg]);
                a[im][2] = f2tf(Ab[(m0)     * ASTR + kb + f.ctg + 4]);
                a[im][3] = f2tf(Ab[(m0 + 8) * ASTR + kb + f.ctg + 4]);
            }
#pragma unroll
            for (int jn = 0; jn < 4; ++jn) {
                const int n0 = b_n0 + jn * 8;
                b[jn][0] = f2tf(Bb[n0 * ASTR + kb + f.ctg]);
                b[jn][1] = f2tf(Bb[n0 * ASTR + kb + f.ctg + 4]);
            }
#pragma unroll
            for (int im = 0; im < 4; ++im)
#pragma unroll
                for (int jn = 0; jn < 4; ++jn)
                    mma_tf32(f.acc[im][jn][0], f.acc[im][jn][1],
                             f.acc[im][jn][2], f.acc[im][jn][3],
                             a[im][0], a[im][1], a[im][2], a[im][3],
                             b[jn][0], b[jn][1]);
        }
        __syncthreads();
    }
}

// ---------------------------------------------------------------------------
// GEMM 1: qkv = x @ attn_w^T + attn_b, scattered head-major into g_qkv.
// ---------------------------------------------------------------------------
__global__ __launch_bounds__(256) void gemm_qkv_kernel(
    const float* __restrict__ A,
    const float* __restrict__ W,
    const float* __restrict__ bias)
{
    __shared__ uint32_t As[4096];
    __shared__ uint32_t Bs[4096];
    const int mBase = blockIdx.y * 128;
    const int nBase = blockIdx.x * 128;

    GemmFrag f;
    gemm_core_frag(A, W, mBase, nBase, As, Bs, f);

#pragma unroll
    for (int im = 0; im < 4; ++im) {
#pragma unroll
        for (int jn = 0; jn < 4; ++jn) {
            const int col = nBase + f.wnB + jn * 8 + 2 * f.ctg;
            const float2 bi = *(const float2*)(bias + col);
            const int which = col / C_;
            const int c = col - which * C_;
            const int h = c / HD_;
            const int d = c - h * HD_;   // even; pair never straddles a head
#pragma unroll
            for (int half = 0; half < 2; ++half) {
                const int row = mBase + f.wmB + im * 16 + f.gid + half * 8;
                const int b = row >> 8;
                const int t = row & 255;
                float2 v;
                v.x = f.acc[im][jn][half * 2 + 0] + bi.x;
                v.y = f.acc[im][jn][half * 2 + 1] + bi.y;
                const size_t dst = (size_t)which * QKV_STRIDE
                                 + ((size_t)((b * NH_ + h) * T_ + t)) * HD_ + d;
                *(float2*)(g_qkv + dst) = v;
            }
        }
    }
}

// ---------------------------------------------------------------------------
// GEMM 2: out = g_att @ proj_w^T + proj_b.
// ---------------------------------------------------------------------------
__global__ __launch_bounds__(256) void gemm_proj_kernel(
    const float* __restrict__ W,
    const float* __restrict__ bias,
    float* __restrict__ out)
{
    __shared__ float As[2 * BUF_ELT];
    __shared__ float Bs[2 * BUF_ELT];
    const int mBase = blockIdx.y * 128;
    const int nBase = blockIdx.x * 128;

    GemmFrag f;
    gemm_core_pipe(g_att, W, mBase, nBase, As, Bs, f);

#pragma unroll
    for (int im = 0; im < 4; ++im) {
#pragma unroll
        for (int jn = 0; jn < 4; ++jn) {
            const int col = nBase + f.wnB + jn * 8 + 2 * f.ctg;
            const float2 bi = *(const float2*)(bias + col);
#pragma unroll
            for (int half = 0; half < 2; ++half) {
                const int row = mBase + f.wmB + im * 16 + f.gid + half * 8;
                float2 v;
                v.x = f.acc[im][jn][half * 2 + 0] + bi.x;
                v.y = f.acc[im][jn][half * 2 + 1] + bi.y;
                *(float2*)(out + (size_t)row * C_ + col) = v;
            }
        }
    }
}

// ---------------------------------------------------------------------------
// Flash attention, tf32 tensor cores (R14 verbatim: prefetch + atom skip).
// ---------------------------------------------------------------------------
#define KSTR 52
#define VSTR 68

__global__ __launch_bounds__(256, 2) void attn_kernel()
{
    __shared__ uint32_t sK[64 * KSTR];
    __shared__ uint32_t sVT[48 * VSTR];

    const int bh = blockIdx.x;
    const int qt = blockIdx.y;
    const int qb = qt * 128;
    const size_t base = (size_t)bh * (T_ * HD_);
    const float* Qg = g_qkv + base;
    const float* Kg = g_qkv + (size_t)QKV_STRIDE + base;
    const float* Vg = g_qkv + 2ull * QKV_STRIDE + base;

    const int tid  = threadIdx.x;
    const int lane = tid & 31;
    const int wid  = tid >> 5;
    const int gid  = lane >> 2;
    const int ctg  = lane & 3;

    const int r0  = wid * 16 + gid;
    const int r1  = r0 + 8;
    const int gr0 = qb + r0;
    const int gr1 = qb + r1;
    const int wtop = qb + wid * 16 + 15;

    const float scale   = 0.14433756729740645f;   // 1/sqrt(48)
    const float NEG_INF = __int_as_float(0xff800000);

    uint32_t aq[6][4];
#pragma unroll
    for (int kb = 0; kb < 6; ++kb) {
        aq[kb][0] = f2tf(Qg[(size_t)gr0 * HD_ + kb * 8 + ctg]     * scale);
        aq[kb][1] = f2tf(Qg[(size_t)gr1 * HD_ + kb * 8 + ctg]     * scale);
        aq[kb][2] = f2tf(Qg[(size_t)gr0 * HD_ + kb * 8 + ctg + 4] * scale);
        aq[kb][3] = f2tf(Qg[(size_t)gr1 * HD_ + kb * 8 + ctg + 4] * scale);
    }

    int srow[3], scol[3];
#pragma unroll
    for (int i = 0; i < 3; ++i) {
        const int idx = tid + i * 256;
        srow[i] = idx / 12;
        scol[i] = (idx % 12) * 4;
    }

    float m0 = NEG_INF, m1 = NEG_INF, l0 = 0.f, l1 = 0.f;
    float o[6][4];
#pragma unroll
    for (int n = 0; n < 6; ++n)
#pragma unroll
        for (int r = 0; r < 4; ++r) o[n][r] = 0.f;

    const int npass = 2 * (qt + 1);

    float4 kreg[3], vreg[3];
#pragma unroll
    for (int i = 0; i < 3; ++i) {
        kreg[i] = *(const float4*)(Kg + (size_t)srow[i] * HD_ + scol[i]);
        vreg[i] = *(const float4*)(Vg + (size_t)srow[i] * HD_ + scol[i]);
    }

    for (int j = 0; j < npass; ++j) {
        const int jb = j * 64;
        __syncthreads();

#pragma unroll
        for (int i = 0; i < 3; ++i) {
            const int r  = srow[i];
            const int c4 = scol[i];
            uint4 kt;
            kt.x = f2tf(kreg[i].x); kt.y = f2tf(kreg[i].y);
            kt.z = f2tf(kreg[i].z); kt.w = f2tf(kreg[i].w);
            *(uint4*)(sK + r * KSTR + c4) = kt;
            sVT[(c4 + 0) * VSTR + r] = f2tf(vreg[i].x);
            sVT[(c4 + 1) * VSTR + r] = f2tf(vreg[i].y);
            sVT[(c4 + 2) * VSTR + r] = f2tf(vreg[i].z);
            sVT[(c4 + 3) * VSTR + r] = f2tf(vreg[i].w);
        }
        __syncthreads();

        if (j + 1 < npass) {
            const int jn2 = (j + 1) * 64;
#pragma unroll
            for (int i = 0; i < 3; ++i) {
                kreg[i] = *(const float4*)(Kg + (size_t)(jn2 + srow[i]) * HD_ + scol[i]);
                vreg[i] = *(const float4*)(Vg + (size_t)(jn2 + srow[i]) * HD_ + scol[i]);
            }
        }

        if (jb > wtop) continue;
        const int nbmax = min(8, ((wtop - jb) >> 3) + 1);

        float s[8][4];
#pragma unroll
        for (int nb = 0; nb < 8; ++nb) {
            if (nb < nbmax) {
                s[nb][0] = 0.f; s[nb][1] = 0.f; s[nb][2] = 0.f; s[nb][3] = 0.f;
#pragma unroll
                for (int kb = 0; kb < 6; ++kb) {
                    const uint32_t b0 = sK[(nb * 8 + gid) * KSTR + kb * 8 + ctg];
                    const uint32_t b1 = sK[(nb * 8 + gid) * KSTR + kb * 8 + ctg + 4];
                    mma_tf32(s[nb][0], s[nb][1], s[nb][2], s[nb][3],
                             aq[kb][0], aq[kb][1], aq[kb][2], aq[kb][3], b0, b1);
                }
            } else {
                s[nb][0] = NEG_INF; s[nb][1] = NEG_INF;
                s[nb][2] = NEG_INF; s[nb][3] = NEG_INF;
            }
        }

        float tmax0 = NEG_INF, tmax1 = NEG_INF;
#pragma unroll
        for (int nb = 0; nb < 8; ++nb) {
            if (nb >= nbmax) continue;
            const int k0 = jb + nb * 8 + 2 * ctg;
            const int k1 = k0 + 1;
            if (k0 > gr0) s[nb][0] = NEG_INF;
            if (k1 > gr0) s[nb][1] = NEG_INF;
            if (k0 > gr1) s[nb][2] = NEG_INF;
            if (k1 > gr1) s[nb][3] = NEG_INF;
            tmax0 = fmaxf(tmax0, fmaxf(s[nb][0], s[nb][1]));
            tmax1 = fmaxf(tmax1, fmaxf(s[nb][2], s[nb][3]));
        }
        tmax0 = fmaxf(tmax0, __shfl_xor_sync(0xffffffffu, tmax0, 1));
        tmax0 = fmaxf(tmax0, __shfl_xor_sync(0xffffffffu, tmax0, 2));
        tmax1 = fmaxf(tmax1, __shfl_xor_sync(0xffffffffu, tmax1, 1));
        tmax1 = fmaxf(tmax1, __shfl_xor_sync(0xffffffffu, tmax1, 2));

        const float mn0 = fmaxf(m0, tmax0);
        const float mn1 = fmaxf(m1, tmax1);
        const float corr0 = __expf(m0 - mn0);
        const float corr1 = __expf(m1 - mn1);
        m0 = mn0; m1 = mn1;

        float ps0 = 0.f, ps1 = 0.f;
#pragma unroll
        for (int nb = 0; nb < 8; ++nb) {
            if (nb >= nbmax) continue;
            s[nb][0] = __expf(s[nb][0] - mn0);
            s[nb][1] = __expf(s[nb][1] - mn0);
            s[nb][2] = __expf(s[nb][2] - mn1);
            s[nb][3] = __expf(s[nb][3] - mn1);
            ps0 += s[nb][0] + s[nb][1];
            ps1 += s[nb][2] + s[nb][3];
        }
        ps0 += __shfl_xor_sync(0xffffffffu, ps0, 1);
        ps0 += __shfl_xor_sync(0xffffffffu, ps0, 2);
        ps1 += __shfl_xor_sync(0xffffffffu, ps1, 1);
        ps1 += __shfl_xor_sync(0xffffffffu, ps1, 2);
        l0 = l0 * corr0 + ps0;
        l1 = l1 * corr1 + ps1;

#pragma unroll
        for (int n = 0; n < 6; ++n) {
            o[n][0] *= corr0; o[n][1] *= corr0;
            o[n][2] *= corr1; o[n][3] *= corr1;
        }

        const int src0 = (lane & ~3) | (ctg >> 1);
        const int src1 = src0 + 2;
        const bool odd = ctg & 1;
#pragma unroll
        for (int kb = 0; kb < 8; ++kb) {
            if (kb >= nbmax) continue;
            const float v00 = __shfl_sync(0xffffffffu, s[kb][0], src0);
            const float v01 = __shfl_sync(0xffffffffu, s[kb][1], src0);
            const float v02 = __shfl_sync(0xffffffffu, s[kb][2], src0);
            const float v03 = __shfl_sync(0xffffffffu, s[kb][3], src0);
            const float v10 = __shfl_sync(0xffffffffu, s[kb][0], src1);
            const float v11 = __shfl_sync(0xffffffffu, s[kb][1], src1);
            const float v12 = __shfl_sync(0xffffffffu, s[kb][2], src1);
            const float v13 = __shfl_sync(0xffffffffu, s[kb][3], src1);
            uint32_t a0 = f2tf(odd ? v01 : v00);
            uint32_t a1 = f2tf(odd ? v03 : v02);
            uint32_t a2 = f2tf(odd ? v11 : v10);
            uint32_t a3 = f2tf(odd ? v13 : v12);
#pragma unroll
            for (int nb = 0; nb < 6; ++nb) {
                const uint32_t b0 = sVT[(nb * 8 + gid) * VSTR + kb * 8 + ctg];
                const uint32_t b1 = sVT[(nb * 8 + gid) * VSTR + kb * 8 + ctg + 4];
                mma_tf32(o[nb][0], o[nb][1], o[nb][2], o[nb][3],
                         a0, a1, a2, a3, b0, b1);
            }
        }
    }

    const float inv0 = 1.f / l0;
    const float inv1 = 1.f / l1;
    const int b = bh >> 3, h = bh & 7;
    float* dst0 = g_att + (size_t)(b * T_ + gr0) * C_ + h * HD_;
    float* dst1 = g_att + (size_t)(b * T_ + gr1) * C_ + h * HD_;
#pragma unroll
    for (int nb = 0; nb < 6; ++nb) {
        const int col = nb * 8 + 2 * ctg;
        float2 v0, v1;
        v0.x = o[nb][0] * inv0; v0.y = o[nb][1] * inv0;
        v1.x = o[nb][2] * inv1; v1.y = o[nb][3] * inv1;
        *(float2*)(dst0 + col) = v0;
        *(float2*)(dst1 + col) = v1;
    }
}

// ---------------------------------------------------------------------------
extern "C" void kernel_launch(void* const* d_in, const int* in_sizes, int n_in,
                              void* d_out, int out_size)
{
    const float* x      = (const float*)d_in[0];
    const float* attn_w = (const float*)d_in[1];
    const float* attn_b = (const float*)d_in[2];
    const float* proj_w = (const float*)d_in[3];
    const float* proj_b = (const float*)d_in[4];
    float* out = (float*)d_out;

    gemm_qkv_kernel<<<dim3(N1_ / 128, M_ / 128), 256>>>(x, attn_w, attn_b);
    attn_kernel<<<dim3(B_ * NH_, 2), 256>>>();
    gemm_proj_kernel<<<dim3(C_ / 128, M_ / 128), 256>>>(proj_w, proj_b, out);
}